// round 5
// baseline (speedup 1.0000x reference)
#include <cuda_runtime.h>
#include <mma.h>
#include <cmath>

using namespace nvcuda;

#define T_TOK 4096
#define NE    8
#define HDIM  2048
#define IDIM  4096
#define TOPK  2
#define NSLOT (T_TOK * TOPK)

#define TM   128
#define TN   64
#define KC   16
#define PADX 24   // sX row stride (floats); 96B, multiple of 16B
#define PADW 72   // sW row stride (floats); 288B, multiple of 16B
#define PADS 20   // staging row stride; 80B, multiple of 16B

// ---------------- scratch (static device memory; no allocations) ----------------
__device__ float g_act[(size_t)NSLOT * IDIM];   // 128 MB activation scratch
__device__ int   g_counts[NE];
__device__ int   g_pos[NE];
__device__ int   g_off[NE + 1];
__device__ int   g_tok_e[T_TOK * TOPK];
__device__ float g_tok_w[T_TOK * TOPK];
__device__ int   g_slot_tok[NSLOT];
__device__ float g_slot_w[NSLOT];

// ---------------- init: zero output + counters ----------------
__global__ void k_init(float* __restrict__ out, int n) {
    int i = blockIdx.x * blockDim.x + threadIdx.x;
    if (i < n) out[i] = 0.f;
    if (i < NE) { g_counts[i] = 0; g_pos[i] = 0; }
}

// ---------------- routing: softmax -> top2 -> renormalize ----------------
__global__ void k_route(const float* __restrict__ logits) {
    int t = blockIdx.x * blockDim.x + threadIdx.x;
    if (t >= T_TOK) return;
    float p[NE];
    float mx = -1e30f;
#pragma unroll
    for (int e = 0; e < NE; e++) { p[e] = logits[t * NE + e]; mx = fmaxf(mx, p[e]); }
#pragma unroll
    for (int e = 0; e < NE; e++) p[e] = expf(p[e] - mx);
    // top-2 (lowest index wins ties, matching jax.lax.top_k)
    int i0 = 0;
#pragma unroll
    for (int e = 1; e < NE; e++) if (p[e] > p[i0]) i0 = e;
    int i1 = (i0 == 0) ? 1 : 0;
#pragma unroll
    for (int e = 0; e < NE; e++) if (e != i0 && p[e] > p[i1]) i1 = e;
    float w0 = p[i0], w1 = p[i1];
    float s = w0 + w1;
    w0 /= s; w1 /= s;
    g_tok_e[t * 2]     = i0;  g_tok_e[t * 2 + 1] = i1;
    g_tok_w[t * 2]     = w0;  g_tok_w[t * 2 + 1] = w1;
    atomicAdd(&g_counts[i0], 1);
    atomicAdd(&g_counts[i1], 1);
}

__global__ void k_scan() {
    int acc = 0;
    for (int e = 0; e < NE; e++) { g_off[e] = acc; acc += g_counts[e]; }
    g_off[NE] = acc;
}

__global__ void k_scatter() {
    int t = blockIdx.x * blockDim.x + threadIdx.x;
    if (t >= T_TOK) return;
#pragma unroll
    for (int j = 0; j < TOPK; j++) {
        int e = g_tok_e[t * 2 + j];
        int pos = atomicAdd(&g_pos[e], 1);
        int s = g_off[e] + pos;
        g_slot_tok[s] = t;
        g_slot_w[s]   = g_tok_w[t * 2 + j];
    }
}

// ---------------- GEMM1: A[slot, 0:I] = silu(Xg @ W1) * (Xg @ W3) ----------------
// grid: (I/TN=64, 32 m-tiles max, E) block: 256 threads (8 warps = 4x2)
__global__ __launch_bounds__(256) void k_gemm1(const float* __restrict__ X,
                                               const float* __restrict__ W13) {
    int e = blockIdx.z;
    int m_beg = g_off[e], m_end = g_off[e + 1];
    int m0 = m_beg + blockIdx.y * TM;
    if (m0 >= m_end) return;
    int n0 = blockIdx.x * TN;   // column within [0, I)

    __shared__ float sX[TM][PADX];
    __shared__ float sW1[KC][PADW];
    __shared__ float sW3[KC][PADW];
    __shared__ float stag[8][16][PADS];
    __shared__ int   stok[TM];

    int tid = threadIdx.x, warp = tid >> 5, lane = tid & 31;
    int wm = warp >> 1;  // 0..3
    int wn = warp & 1;   // 0..1

    if (tid < TM) {
        int gr = m0 + tid;
        stok[tid] = (gr < m_end) ? g_slot_tok[gr] : -1;
    }
    __syncthreads();

    wmma::fragment<wmma::accumulator, 16, 16, 8, float> accg[2][2], accu[2][2];
#pragma unroll
    for (int i = 0; i < 2; i++)
#pragma unroll
        for (int j = 0; j < 2; j++) {
            wmma::fill_fragment(accg[i][j], 0.f);
            wmma::fill_fragment(accu[i][j], 0.f);
        }

    const float* Wbase = W13 + (size_t)e * HDIM * (2 * IDIM);

    for (int k0 = 0; k0 < HDIM; k0 += KC) {
        // X tile: 128 rows x 16 cols -> 512 float4, 2 per thread
#pragma unroll
        for (int it = 0; it < 2; it++) {
            int f = tid + it * 256;
            int r = f >> 2, seg = f & 3;
            int tok = stok[r];
            float4 v = make_float4(0.f, 0.f, 0.f, 0.f);
            if (tok >= 0) v = *(const float4*)&X[(size_t)tok * HDIM + k0 + seg * 4];
            *(float4*)&sX[r][seg * 4] = v;
        }
        // W1/W3 tiles: 16 x 64 each -> 256 float4 each, 1 each per thread
        {
            int r = tid >> 4, seg = tid & 15;
            const float* p = Wbase + (size_t)(k0 + r) * (2 * IDIM) + n0 + seg * 4;
            *(float4*)&sW1[r][seg * 4] = *(const float4*)p;
            *(float4*)&sW3[r][seg * 4] = *(const float4*)(p + IDIM);
        }
        __syncthreads();

#pragma unroll
        for (int kk = 0; kk < KC; kk += 8) {
            wmma::fragment<wmma::matrix_a, 16, 16, 8, wmma::precision::tf32, wmma::row_major> a[2];
            wmma::fragment<wmma::matrix_b, 16, 16, 8, wmma::precision::tf32, wmma::row_major> bg[2], bu[2];
#pragma unroll
            for (int i = 0; i < 2; i++) {
                wmma::load_matrix_sync(a[i], &sX[wm * 32 + i * 16][kk], PADX);
#pragma unroll
                for (int x = 0; x < a[i].num_elements; x++)
                    a[i].x[x] = wmma::__float_to_tf32(a[i].x[x]);
            }
#pragma unroll
            for (int j = 0; j < 2; j++) {
                wmma::load_matrix_sync(bg[j], &sW1[kk][wn * 32 + j * 16], PADW);
                wmma::load_matrix_sync(bu[j], &sW3[kk][wn * 32 + j * 16], PADW);
#pragma unroll
                for (int x = 0; x < bg[j].num_elements; x++) {
                    bg[j].x[x] = wmma::__float_to_tf32(bg[j].x[x]);
                    bu[j].x[x] = wmma::__float_to_tf32(bu[j].x[x]);
                }
            }
#pragma unroll
            for (int i = 0; i < 2; i++)
#pragma unroll
                for (int j = 0; j < 2; j++) {
                    wmma::mma_sync(accg[i][j], a[i], bg[j], accg[i][j]);
                    wmma::mma_sync(accu[i][j], a[i], bu[j], accu[i][j]);
                }
        }
        __syncthreads();
    }

    // epilogue: act = silu(gate) * up, computed in-fragment (identical layouts)
#pragma unroll
    for (int i = 0; i < 2; i++)
#pragma unroll
        for (int j = 0; j < 2; j++) {
#pragma unroll
            for (int x = 0; x < accg[i][j].num_elements; x++) {
                float g = accg[i][j].x[x];
                float u = accu[i][j].x[x];
                accg[i][j].x[x] = (g / (1.f + expf(-g))) * u;
            }
            wmma::store_matrix_sync(&stag[warp][0][0], accg[i][j], PADS, wmma::mem_row_major);
            __syncwarp();
            int r0 = wm * 32 + i * 16;
            int c0 = n0 + wn * 32 + j * 16;
#pragma unroll
            for (int q = 0; q < 8; q++) {
                int idx = q * 32 + lane;
                int rr = idx >> 4, cc = idx & 15;
                int gr = m0 + r0 + rr;
                if (gr < m_end)
                    g_act[(size_t)gr * IDIM + c0 + cc] = stag[warp][rr][cc];
            }
            __syncwarp();
        }
}

// ---------------- GEMM2: out[tok] += w * (A[slot] @ W2[e]) ----------------
// grid: (H/64=32, 32 m-tiles max, E)
__global__ __launch_bounds__(256) void k_gemm2(const float* __restrict__ W2,
                                               float* __restrict__ out) {
    int e = blockIdx.z;
    int m_beg = g_off[e], m_end = g_off[e + 1];
    int m0 = m_beg + blockIdx.y * TM;
    if (m0 >= m_end) return;
    int n0 = blockIdx.x * TN;   // column within [0, H)

    __shared__ float sA[TM][PADX];
    __shared__ float sW[KC][PADW];
    __shared__ float stag[8][16][PADS];
    __shared__ int   stok[TM];
    __shared__ float swt[TM];

    int tid = threadIdx.x, warp = tid >> 5, lane = tid & 31;
    int wm = warp >> 1;
    int wn = warp & 1;

    if (tid < TM) {
        int gr = m0 + tid;
        bool v = (gr < m_end);
        stok[tid] = v ? g_slot_tok[gr] : -1;
        swt[tid]  = v ? g_slot_w[gr]   : 0.f;
    }
    __syncthreads();

    wmma::fragment<wmma::accumulator, 16, 16, 8, float> acc[2][2];
#pragma unroll
    for (int i = 0; i < 2; i++)
#pragma unroll
        for (int j = 0; j < 2; j++)
            wmma::fill_fragment(acc[i][j], 0.f);

    const float* Wbase = W2 + (size_t)e * IDIM * HDIM;

    for (int k0 = 0; k0 < IDIM; k0 += KC) {
        // A tile (contiguous slots, no gather)
#pragma unroll
        for (int it = 0; it < 2; it++) {
            int f = tid + it * 256;
            int r = f >> 2, seg = f & 3;
            int gr = m0 + r;
            float4 v = make_float4(0.f, 0.f, 0.f, 0.f);
            if (gr < m_end) v = *(const float4*)&g_act[(size_t)gr * IDIM + k0 + seg * 4];
            *(float4*)&sA[r][seg * 4] = v;
        }
        // W2 tile: 16 x 64 -> 256 float4, 1 per thread
        {
            int r = tid >> 4, seg = tid & 15;
            *(float4*)&sW[r][seg * 4] =
                *(const float4*)&Wbase[(size_t)(k0 + r) * HDIM + n0 + seg * 4];
        }
        __syncthreads();

#pragma unroll
        for (int kk = 0; kk < KC; kk += 8) {
            wmma::fragment<wmma::matrix_a, 16, 16, 8, wmma::precision::tf32, wmma::row_major> a[2];
            wmma::fragment<wmma::matrix_b, 16, 16, 8, wmma::precision::tf32, wmma::row_major> b[2];
#pragma unroll
            for (int i = 0; i < 2; i++) {
                wmma::load_matrix_sync(a[i], &sA[wm * 32 + i * 16][kk], PADX);
#pragma unroll
                for (int x = 0; x < a[i].num_elements; x++)
                    a[i].x[x] = wmma::__float_to_tf32(a[i].x[x]);
            }
#pragma unroll
            for (int j = 0; j < 2; j++) {
                wmma::load_matrix_sync(b[j], &sW[kk][wn * 32 + j * 16], PADW);
#pragma unroll
                for (int x = 0; x < b[j].num_elements; x++)
                    b[j].x[x] = wmma::__float_to_tf32(b[j].x[x]);
            }
#pragma unroll
            for (int i = 0; i < 2; i++)
#pragma unroll
                for (int j = 0; j < 2; j++)
                    wmma::mma_sync(acc[i][j], a[i], b[j], acc[i][j]);
        }
        __syncthreads();
    }

    // epilogue: weighted atomic scatter into out[tok, :]
#pragma unroll
    for (int i = 0; i < 2; i++)
#pragma unroll
        for (int j = 0; j < 2; j++) {
            wmma::store_matrix_sync(&stag[warp][0][0], acc[i][j], PADS, wmma::mem_row_major);
            __syncwarp();
            int r0 = wm * 32 + i * 16;
            int c0 = n0 + wn * 32 + j * 16;
#pragma unroll
            for (int q = 0; q < 8; q++) {
                int idx = q * 32 + lane;
                int rr = idx >> 4, cc = idx & 15;
                int gr = m0 + r0 + rr;
                if (gr < m_end) {
                    int tok = stok[r0 + rr];
                    float v = stag[warp][rr][cc] * swt[r0 + rr];
                    atomicAdd(&out[(size_t)tok * HDIM + c0 + cc], v);
                }
            }
            __syncwarp();
        }
}

// ---------------- launch ----------------
extern "C" void kernel_launch(void* const* d_in, const int* in_sizes, int n_in,
                              void* d_out, int out_size) {
    const float* X      = (const float*)d_in[0];
    const float* logits = (const float*)d_in[1];
    const float* W13    = (const float*)d_in[2];
    const float* W2     = (const float*)d_in[3];
    float* out = (float*)d_out;

    int n_out = T_TOK * HDIM;
    k_init<<<(n_out + 1023) / 1024, 1024>>>(out, n_out);
    k_route<<<(T_TOK + 255) / 256, 256>>>(logits);
    k_scan<<<1, 1>>>();
    k_scatter<<<(T_TOK + 255) / 256, 256>>>();

    dim3 g1(IDIM / TN, (T_TOK + TM - 1) / TM, NE);   // (64, 32, 8)
    k_gemm1<<<g1, 256>>>(X, W13);

    dim3 g2(HDIM / TN, (T_TOK + TM - 1) / TM, NE);   // (32, 32, 8)
    k_gemm2<<<g2, 256>>>(W2, out);
}

// round 6
// speedup vs baseline: 1.5693x; 1.5693x over previous
#include <cuda_runtime.h>
#include <mma.h>
#include <cmath>

using namespace nvcuda;

#define T_TOK 4096
#define NE    8
#define HDIM  2048
#define IDIM  4096
#define TOPK  2
#define NSLOT (T_TOK * TOPK)

#define TM   128
#define TN   64
#define KC   16
#define PX   20   // sX row stride (floats)
#define PW   68   // sW row stride (floats)
#define PS   16   // staging row stride (floats)

// ---------------- scratch (static device memory; no allocations) ----------------
__device__ float g_act[(size_t)NSLOT * IDIM];   // 128 MB activation scratch
__device__ int   g_counts[NE];
__device__ int   g_pos[NE];
__device__ int   g_off[NE + 1];
__device__ int   g_tok_e[T_TOK * TOPK];
__device__ float g_tok_w[T_TOK * TOPK];
__device__ int   g_slot_tok[NSLOT];
__device__ float g_slot_w[NSLOT];

__device__ __forceinline__ float4 cvt4_tf32(float4 v) {
    v.x = wmma::__float_to_tf32(v.x);
    v.y = wmma::__float_to_tf32(v.y);
    v.z = wmma::__float_to_tf32(v.z);
    v.w = wmma::__float_to_tf32(v.w);
    return v;
}

// ---------------- init: zero output + counters ----------------
__global__ void k_init(float* __restrict__ out, int n) {
    int i = blockIdx.x * blockDim.x + threadIdx.x;
    if (i < n) out[i] = 0.f;
    if (i < NE) { g_counts[i] = 0; g_pos[i] = 0; }
}

// ---------------- routing: softmax -> top2 -> renormalize ----------------
__global__ void k_route(const float* __restrict__ logits) {
    int t = blockIdx.x * blockDim.x + threadIdx.x;
    if (t >= T_TOK) return;
    float p[NE];
    float mx = -1e30f;
#pragma unroll
    for (int e = 0; e < NE; e++) { p[e] = logits[t * NE + e]; mx = fmaxf(mx, p[e]); }
#pragma unroll
    for (int e = 0; e < NE; e++) p[e] = expf(p[e] - mx);
    int i0 = 0;
#pragma unroll
    for (int e = 1; e < NE; e++) if (p[e] > p[i0]) i0 = e;
    int i1 = (i0 == 0) ? 1 : 0;
#pragma unroll
    for (int e = 0; e < NE; e++) if (e != i0 && p[e] > p[i1]) i1 = e;
    float w0 = p[i0], w1 = p[i1];
    float s = w0 + w1;
    w0 /= s; w1 /= s;
    g_tok_e[t * 2]     = i0;  g_tok_e[t * 2 + 1] = i1;
    g_tok_w[t * 2]     = w0;  g_tok_w[t * 2 + 1] = w1;
    atomicAdd(&g_counts[i0], 1);
    atomicAdd(&g_counts[i1], 1);
}

__global__ void k_scan() {
    int acc = 0;
    for (int e = 0; e < NE; e++) { g_off[e] = acc; acc += g_counts[e]; }
    g_off[NE] = acc;
}

__global__ void k_scatter() {
    int t = blockIdx.x * blockDim.x + threadIdx.x;
    if (t >= T_TOK) return;
#pragma unroll
    for (int j = 0; j < TOPK; j++) {
        int e = g_tok_e[t * 2 + j];
        int pos = atomicAdd(&g_pos[e], 1);
        int s = g_off[e] + pos;
        g_slot_tok[s] = t;
        g_slot_w[s]   = g_tok_w[t * 2 + j];
    }
}

// ---------------- GEMM1: A[slot, 0:I] = silu(Xg @ W1) * (Xg @ W3) ----------------
// grid: (I/TN=64, 32 m-tiles max, E) block: 256 threads (8 warps = 4x2)
// double-buffered software pipeline; tf32 conversion done at SMEM-store time.
__global__ __launch_bounds__(256) void k_gemm1(const float* __restrict__ X,
                                               const float* __restrict__ W13) {
    int e = blockIdx.z;
    int m_beg = g_off[e], m_end = g_off[e + 1];
    int m0 = m_beg + blockIdx.y * TM;
    if (m0 >= m_end) return;
    int n0 = blockIdx.x * TN;

    __shared__ float sX[2][TM][PX];
    __shared__ float sW1[2][KC][PW];
    __shared__ float sW3[2][KC][PW];
    __shared__ float stag[8][16][PS];
    __shared__ int   stok[TM];

    int tid = threadIdx.x, warp = tid >> 5, lane = tid & 31;
    int wm = warp >> 1;  // 0..3
    int wn = warp & 1;   // 0..1

    if (tid < TM) {
        int gr = m0 + tid;
        stok[tid] = (gr < m_end) ? g_slot_tok[gr] : -1;
    }
    __syncthreads();

    // per-thread load addressing
    int xr = tid >> 2;          // X rows 0..63 (+64 for second half)
    int xs = (tid & 3) * 4;     // X col segment
    int wr = tid >> 4;          // W row 0..15
    int ws = (tid & 15) * 4;    // W col segment
    int tok0 = stok[xr];
    int tok1 = stok[xr + 64];

    wmma::fragment<wmma::accumulator, 16, 16, 8, float> accg[2][2], accu[2][2];
#pragma unroll
    for (int i = 0; i < 2; i++)
#pragma unroll
        for (int j = 0; j < 2; j++) {
            wmma::fill_fragment(accg[i][j], 0.f);
            wmma::fill_fragment(accu[i][j], 0.f);
        }

    const float* Wbase = W13 + (size_t)e * HDIM * (2 * IDIM);
    const float4 Z4 = make_float4(0.f, 0.f, 0.f, 0.f);

    // prologue: chunk 0 -> regs -> cvt -> buf 0
    float4 rx0 = Z4, rx1 = Z4, rw1v, rw3v;
    {
        if (tok0 >= 0) rx0 = *(const float4*)&X[(size_t)tok0 * HDIM + xs];
        if (tok1 >= 0) rx1 = *(const float4*)&X[(size_t)tok1 * HDIM + xs];
        const float* p = Wbase + (size_t)wr * (2 * IDIM) + n0 + ws;
        rw1v = *(const float4*)p;
        rw3v = *(const float4*)(p + IDIM);
        *(float4*)&sX[0][xr][xs]      = cvt4_tf32(rx0);
        *(float4*)&sX[0][xr + 64][xs] = cvt4_tf32(rx1);
        *(float4*)&sW1[0][wr][ws]     = cvt4_tf32(rw1v);
        *(float4*)&sW3[0][wr][ws]     = cvt4_tf32(rw3v);
    }
    __syncthreads();

    const int NKC = HDIM / KC;   // 128
    for (int kc = 0; kc < NKC; kc++) {
        int cur = kc & 1;
        bool more = (kc + 1 < NKC);
        float4 nx0 = Z4, nx1 = Z4, nw1, nw3;
        if (more) {
            int k0 = (kc + 1) * KC;
            if (tok0 >= 0) nx0 = *(const float4*)&X[(size_t)tok0 * HDIM + k0 + xs];
            if (tok1 >= 0) nx1 = *(const float4*)&X[(size_t)tok1 * HDIM + k0 + xs];
            const float* p = Wbase + (size_t)(k0 + wr) * (2 * IDIM) + n0 + ws;
            nw1 = *(const float4*)p;
            nw3 = *(const float4*)(p + IDIM);
        }

        // compute on buffer `cur` (values already tf32-rounded; no in-loop cvt)
#pragma unroll
        for (int kk = 0; kk < KC; kk += 8) {
            wmma::fragment<wmma::matrix_a, 16, 16, 8, wmma::precision::tf32, wmma::row_major> a[2];
            wmma::fragment<wmma::matrix_b, 16, 16, 8, wmma::precision::tf32, wmma::row_major> bg[2], bu[2];
#pragma unroll
            for (int i = 0; i < 2; i++)
                wmma::load_matrix_sync(a[i], &sX[cur][wm * 32 + i * 16][kk], PX);
#pragma unroll
            for (int j = 0; j < 2; j++) {
                wmma::load_matrix_sync(bg[j], &sW1[cur][kk][wn * 32 + j * 16], PW);
                wmma::load_matrix_sync(bu[j], &sW3[cur][kk][wn * 32 + j * 16], PW);
            }
#pragma unroll
            for (int i = 0; i < 2; i++)
#pragma unroll
                for (int j = 0; j < 2; j++) {
                    wmma::mma_sync(accg[i][j], a[i], bg[j], accg[i][j]);
                    wmma::mma_sync(accu[i][j], a[i], bu[j], accu[i][j]);
                }
        }

        if (more) {
            int nxt = cur ^ 1;
            *(float4*)&sX[nxt][xr][xs]      = cvt4_tf32(nx0);
            *(float4*)&sX[nxt][xr + 64][xs] = cvt4_tf32(nx1);
            *(float4*)&sW1[nxt][wr][ws]     = cvt4_tf32(nw1);
            *(float4*)&sW3[nxt][wr][ws]     = cvt4_tf32(nw3);
        }
        __syncthreads();
    }

    // epilogue: act = silu(gate) * up, computed in-fragment
#pragma unroll
    for (int i = 0; i < 2; i++)
#pragma unroll
        for (int j = 0; j < 2; j++) {
#pragma unroll
            for (int x = 0; x < accg[i][j].num_elements; x++) {
                float g = accg[i][j].x[x];
                float u = accu[i][j].x[x];
                accg[i][j].x[x] = (g / (1.f + expf(-g))) * u;
            }
            wmma::store_matrix_sync(&stag[warp][0][0], accg[i][j], PS, wmma::mem_row_major);
            __syncwarp();
            int r0 = wm * 32 + i * 16;
            int c0 = n0 + wn * 32 + j * 16;
#pragma unroll
            for (int q = 0; q < 8; q++) {
                int idx = q * 32 + lane;
                int rr = idx >> 4, cc = idx & 15;
                int gr = m0 + r0 + rr;
                if (gr < m_end)
                    g_act[(size_t)gr * IDIM + c0 + cc] = stag[warp][rr][cc];
            }
            __syncwarp();
        }
}

// ---------------- GEMM2: out[tok] += w * (A[slot] @ W2[e]) ----------------
// grid: (H/64=32, 32 m-tiles max, E)
__global__ __launch_bounds__(256) void k_gemm2(const float* __restrict__ W2,
                                               float* __restrict__ out) {
    int e = blockIdx.z;
    int m_beg = g_off[e], m_end = g_off[e + 1];
    int m0 = m_beg + blockIdx.y * TM;
    if (m0 >= m_end) return;
    int n0 = blockIdx.x * TN;

    __shared__ float sA[2][TM][PX];
    __shared__ float sW[2][KC][PW];
    __shared__ float stag[8][16][PS];
    __shared__ int   stok[TM];
    __shared__ float swt[TM];

    int tid = threadIdx.x, warp = tid >> 5, lane = tid & 31;
    int wm = warp >> 1;
    int wn = warp & 1;

    if (tid < TM) {
        int gr = m0 + tid;
        bool v = (gr < m_end);
        stok[tid] = v ? g_slot_tok[gr] : -1;
        swt[tid]  = v ? g_slot_w[gr]   : 0.f;
    }
    __syncthreads();

    int xr = tid >> 2;
    int xs = (tid & 3) * 4;
    int wr = tid >> 4;
    int ws = (tid & 15) * 4;
    bool v0 = (m0 + xr)      < m_end;
    bool v1 = (m0 + xr + 64) < m_end;

    wmma::fragment<wmma::accumulator, 16, 16, 8, float> acc[2][2];
#pragma unroll
    for (int i = 0; i < 2; i++)
#pragma unroll
        for (int j = 0; j < 2; j++)
            wmma::fill_fragment(acc[i][j], 0.f);

    const float* Wbase = W2 + (size_t)e * IDIM * HDIM;
    const float4 Z4 = make_float4(0.f, 0.f, 0.f, 0.f);

    // prologue
    {
        float4 ra0 = Z4, ra1 = Z4;
        if (v0) ra0 = *(const float4*)&g_act[(size_t)(m0 + xr)      * IDIM + xs];
        if (v1) ra1 = *(const float4*)&g_act[(size_t)(m0 + xr + 64) * IDIM + xs];
        float4 rw = *(const float4*)&Wbase[(size_t)wr * HDIM + n0 + ws];
        *(float4*)&sA[0][xr][xs]      = cvt4_tf32(ra0);
        *(float4*)&sA[0][xr + 64][xs] = cvt4_tf32(ra1);
        *(float4*)&sW[0][wr][ws]      = cvt4_tf32(rw);
    }
    __syncthreads();

    const int NKC = IDIM / KC;   // 256
    for (int kc = 0; kc < NKC; kc++) {
        int cur = kc & 1;
        bool more = (kc + 1 < NKC);
        float4 na0 = Z4, na1 = Z4, nw;
        if (more) {
            int k0 = (kc + 1) * KC;
            if (v0) na0 = *(const float4*)&g_act[(size_t)(m0 + xr)      * IDIM + k0 + xs];
            if (v1) na1 = *(const float4*)&g_act[(size_t)(m0 + xr + 64) * IDIM + k0 + xs];
            nw = *(const float4*)&Wbase[(size_t)(k0 + wr) * HDIM + n0 + ws];
        }

#pragma unroll
        for (int kk = 0; kk < KC; kk += 8) {
            wmma::fragment<wmma::matrix_a, 16, 16, 8, wmma::precision::tf32, wmma::row_major> a[2];
            wmma::fragment<wmma::matrix_b, 16, 16, 8, wmma::precision::tf32, wmma::row_major> b[2];
#pragma unroll
            for (int i = 0; i < 2; i++)
                wmma::load_matrix_sync(a[i], &sA[cur][wm * 32 + i * 16][kk], PX);
#pragma unroll
            for (int j = 0; j < 2; j++)
                wmma::load_matrix_sync(b[j], &sW[cur][kk][wn * 32 + j * 16], PW);
#pragma unroll
            for (int i = 0; i < 2; i++)
#pragma unroll
                for (int j = 0; j < 2; j++)
                    wmma::mma_sync(acc[i][j], a[i], b[j], acc[i][j]);
        }

        if (more) {
            int nxt = cur ^ 1;
            *(float4*)&sA[nxt][xr][xs]      = cvt4_tf32(na0);
            *(float4*)&sA[nxt][xr + 64][xs] = cvt4_tf32(na1);
            *(float4*)&sW[nxt][wr][ws]      = cvt4_tf32(nw);
        }
        __syncthreads();
    }

    // epilogue: weighted atomic scatter into out[tok, :]
#pragma unroll
    for (int i = 0; i < 2; i++)
#pragma unroll
        for (int j = 0; j < 2; j++) {
            wmma::store_matrix_sync(&stag[warp][0][0], acc[i][j], PS, wmma::mem_row_major);
            __syncwarp();
            int r0 = wm * 32 + i * 16;
            int c0 = n0 + wn * 32 + j * 16;
#pragma unroll
            for (int q = 0; q < 8; q++) {
                int idx = q * 32 + lane;
                int rr = idx >> 4, cc = idx & 15;
                int gr = m0 + r0 + rr;
                if (gr < m_end) {
                    int tok = stok[r0 + rr];
                    float v = stag[warp][rr][cc] * swt[r0 + rr];
                    atomicAdd(&out[(size_t)tok * HDIM + c0 + cc], v);
                }
            }
            __syncwarp();
        }
}

// ---------------- launch ----------------
extern "C" void kernel_launch(void* const* d_in, const int* in_sizes, int n_in,
                              void* d_out, int out_size) {
    const float* X      = (const float*)d_in[0];
    const float* logits = (const float*)d_in[1];
    const float* W13    = (const float*)d_in[2];
    const float* W2     = (const float*)d_in[3];
    float* out = (float*)d_out;

    int n_out = T_TOK * HDIM;
    k_init<<<(n_out + 1023) / 1024, 1024>>>(out, n_out);
    k_route<<<(T_TOK + 255) / 256, 256>>>(logits);
    k_scan<<<1, 1>>>();
    k_scatter<<<(T_TOK + 255) / 256, 256>>>();

    dim3 g1(IDIM / TN, (T_TOK + TM - 1) / TM, NE);   // (64, 32, 8)
    k_gemm1<<<g1, 256>>>(X, W13);

    dim3 g2(HDIM / TN, (T_TOK + TM - 1) / TM, NE);   // (32, 32, 8)
    k_gemm2<<<g2, 256>>>(W2, out);
}

// round 8
// speedup vs baseline: 2.1936x; 1.3978x over previous
#include <cuda_runtime.h>
#include <cstdint>
#include <cmath>

#define T_TOK 4096
#define NE    8
#define HDIM  2048
#define IDIM  4096
#define TOPK  2
#define NSLOT (T_TOK * TOPK)

#define TM    128
#define KC    32
#define SA    36            // A smem row stride (floats): banks 4g+t4 -> conflict-free
#define SB    136           // B smem row stride (floats): banks 8k+g -> conflict-free

#define A_FLOATS (TM * SA)          // 4608
#define B_FLOATS (KC * SB)          // 4352
#define STAGE_FLOATS (A_FLOATS + B_FLOATS)
#define SMEM_BYTES (2 * STAGE_FLOATS * 4)   // 71680

// ---------------- scratch (static device memory; no allocations) ----------------
__device__ float g_act[(size_t)NSLOT * IDIM];   // 128 MB activation scratch
__device__ int   g_counts[NE];
__device__ int   g_pos[NE];
__device__ int   g_off[NE + 1];
__device__ int   g_tok_e[T_TOK * TOPK];
__device__ float g_tok_w[T_TOK * TOPK];
__device__ int   g_slot_tok[NSLOT];
__device__ float g_slot_w[NSLOT];

// ---------------- helpers ----------------
__device__ __forceinline__ unsigned f2tf(float x) {
    unsigned r;
    asm("cvt.rna.tf32.f32 %0, %1;" : "=r"(r) : "f"(x));
    return r;
}
__device__ __forceinline__ uint4 cvt4(float4 v) {
    uint4 r;
    r.x = f2tf(v.x); r.y = f2tf(v.y); r.z = f2tf(v.z); r.w = f2tf(v.w);
    return r;
}
__device__ __forceinline__ void mma8(float* d, const unsigned* a, const unsigned* b) {
    asm volatile(
        "mma.sync.aligned.m16n8k8.row.col.f32.tf32.tf32.f32 "
        "{%0,%1,%2,%3}, {%4,%5,%6,%7}, {%8,%9}, {%0,%1,%2,%3};"
        : "+f"(d[0]), "+f"(d[1]), "+f"(d[2]), "+f"(d[3])
        : "r"(a[0]), "r"(a[1]), "r"(a[2]), "r"(a[3]), "r"(b[0]), "r"(b[1]));
}

// ---------------- small kernels ----------------
__global__ void k_init(float* __restrict__ out, int n) {
    int i = blockIdx.x * blockDim.x + threadIdx.x;
    if (i < n) out[i] = 0.f;
    if (i < NE) { g_counts[i] = 0; g_pos[i] = 0; }
}

__global__ void k_route(const float* __restrict__ logits) {
    int t = blockIdx.x * blockDim.x + threadIdx.x;
    if (t >= T_TOK) return;
    float p[NE];
    float mx = -1e30f;
#pragma unroll
    for (int e = 0; e < NE; e++) { p[e] = logits[t * NE + e]; mx = fmaxf(mx, p[e]); }
#pragma unroll
    for (int e = 0; e < NE; e++) p[e] = expf(p[e] - mx);
    int i0 = 0;
#pragma unroll
    for (int e = 1; e < NE; e++) if (p[e] > p[i0]) i0 = e;
    int i1 = (i0 == 0) ? 1 : 0;
#pragma unroll
    for (int e = 0; e < NE; e++) if (e != i0 && p[e] > p[i1]) i1 = e;
    float w0 = p[i0], w1 = p[i1];
    float s = w0 + w1;
    w0 /= s; w1 /= s;
    g_tok_e[t * 2] = i0;  g_tok_e[t * 2 + 1] = i1;
    g_tok_w[t * 2] = w0;  g_tok_w[t * 2 + 1] = w1;
    atomicAdd(&g_counts[i0], 1);
    atomicAdd(&g_counts[i1], 1);
}

__global__ void k_scan() {
    int acc = 0;
    for (int e = 0; e < NE; e++) { g_off[e] = acc; acc += g_counts[e]; }
    g_off[NE] = acc;
}

__global__ void k_scatter() {
    int t = blockIdx.x * blockDim.x + threadIdx.x;
    if (t >= T_TOK) return;
#pragma unroll
    for (int j = 0; j < TOPK; j++) {
        int e = g_tok_e[t * 2 + j];
        int pos = atomicAdd(&g_pos[e], 1);
        int s = g_off[e] + pos;
        g_slot_tok[s] = t;
        g_slot_w[s]   = g_tok_w[t * 2 + j];
    }
}

// ---------------- GEMM1: A[slot, n0:n0+64] = silu(Xg@W1)*(Xg@W3) ----------------
// block 128m x (64 gate + 64 up) B-cols; 8 warps = 4m x 2n; warp m32 x (32g+32u)
// grid: (32 m-tiles, IDIM/64 = 64 n-tiles, NE)
__global__ __launch_bounds__(256) void k_gemm1(const float* __restrict__ X,
                                               const float* __restrict__ W13) {
    int e = blockIdx.z;
    int m_beg = g_off[e], m_end = g_off[e + 1];
    int m0 = m_beg + blockIdx.x * TM;
    if (m0 >= m_end) return;
    int n0 = blockIdx.y * 64;

    extern __shared__ __align__(16) float smem[];
    float* bufA[2] = { smem,                 smem + STAGE_FLOATS };
    float* bufB[2] = { smem + A_FLOATS,      smem + STAGE_FLOATS + A_FLOATS };

    __shared__ int stok[TM];

    int tid = threadIdx.x, warp = tid >> 5, lane = tid & 31;
    int wm = warp >> 1, wn = warp & 1;
    int g = lane >> 2, t4 = lane & 3;

    if (tid < TM) {
        int gr = m0 + tid;
        stok[tid] = (gr < m_end) ? g_slot_tok[gr] : -1;
    }
    __syncthreads();

    // staging addressing
    int ar = tid >> 1, ah = tid & 1;                  // A: row 0..127, half 0/1
    int tok = stok[ar];
    const float* aptr = X + (size_t)(tok < 0 ? 0 : tok) * HDIM + ah * 16;
    int sAoff = ar * SA + ah * 16;

    int bk = tid >> 3, bg = tid & 7;                  // B: k-row 0..31, 16-col group
    const float* wbase = W13 + (size_t)e * HDIM * (2 * IDIM);
    int ncol = (bg < 4) ? (n0 + bg * 16) : (IDIM + n0 + (bg - 4) * 16);
    const float* bptr = wbase + (size_t)bk * (2 * IDIM) + ncol;
    int sBoff = bk * SB + bg * 16;
    const size_t bstride = (size_t)KC * (2 * IDIM);   // advance 32 k-rows

    float accG[2][4][4], accU[2][4][4];
#pragma unroll
    for (int mt = 0; mt < 2; mt++)
#pragma unroll
        for (int q = 0; q < 4; q++)
#pragma unroll
            for (int x = 0; x < 4; x++) { accG[mt][q][x] = 0.f; accU[mt][q][x] = 0.f; }

    float4 sa[4], sb[4];

    // ---- prologue: stage 0 ----
#pragma unroll
    for (int j = 0; j < 4; j++) {
        sa[j] = *(const float4*)(aptr + 4 * j);
        sb[j] = *(const float4*)(bptr + 4 * j);
    }
#pragma unroll
    for (int j = 0; j < 4; j++) {
        *(uint4*)(bufA[0] + sAoff + 4 * j) = cvt4(sa[j]);
        *(uint4*)(bufB[0] + sBoff + 4 * j) = cvt4(sb[j]);
    }
    __syncthreads();

    const int NI = HDIM / KC;   // 64
    for (int kc = 0; kc < NI; kc++) {
        int cur = kc & 1;
        bool more = (kc + 1 < NI);
        if (more) {
            const float* ap = aptr + (kc + 1) * KC;
            const float* bp = bptr + (size_t)(kc + 1) * bstride;
#pragma unroll
            for (int j = 0; j < 4; j++) {
                sa[j] = *(const float4*)(ap + 4 * j);
                sb[j] = *(const float4*)(bp + 4 * j);
            }
        }

        const float* cA = bufA[cur];
        const float* cB = bufB[cur];
#pragma unroll
        for (int ks = 0; ks < 4; ks++) {
            int k = ks * 8;
            unsigned af[2][4];
#pragma unroll
            for (int mt = 0; mt < 2; mt++) {
                int r0 = (wm * 32 + mt * 16 + g) * SA + k + t4;
                af[mt][0] = *(const unsigned*)(cA + r0);
                af[mt][1] = *(const unsigned*)(cA + r0 + 8 * SA);
                af[mt][2] = *(const unsigned*)(cA + r0 + 4);
                af[mt][3] = *(const unsigned*)(cA + r0 + 8 * SA + 4);
            }
#pragma unroll
            for (int q = 0; q < 4; q++) {
                // gate frag (smem cols 32*wn + 8q), up frag (cols 64 + 32*wn + 8q)
                int cbg = wn * 32 + q * 8 + g;
                int cbu = 64 + wn * 32 + q * 8 + g;
                unsigned bgf[2], buf_[2];
                bgf[0]  = *(const unsigned*)(cB + (k + t4) * SB + cbg);
                bgf[1]  = *(const unsigned*)(cB + (k + t4 + 4) * SB + cbg);
                buf_[0] = *(const unsigned*)(cB + (k + t4) * SB + cbu);
                buf_[1] = *(const unsigned*)(cB + (k + t4 + 4) * SB + cbu);
#pragma unroll
                for (int mt = 0; mt < 2; mt++) {
                    mma8(accG[mt][q], af[mt], bgf);
                    mma8(accU[mt][q], af[mt], buf_);
                }
            }
        }

        if (more) {
            int nxt = cur ^ 1;
#pragma unroll
            for (int j = 0; j < 4; j++) {
                *(uint4*)(bufA[nxt] + sAoff + 4 * j) = cvt4(sa[j]);
                *(uint4*)(bufB[nxt] + sBoff + 4 * j) = cvt4(sb[j]);
            }
        }
        __syncthreads();
    }

    // ---- epilogue: silu(gate)*up -> g_act (float2 stores, coalesced) ----
#pragma unroll
    for (int mt = 0; mt < 2; mt++) {
        int R0 = m0 + wm * 32 + mt * 16 + g;
        int R1 = R0 + 8;
#pragma unroll
        for (int q = 0; q < 4; q++) {
            int col = n0 + wn * 32 + q * 8 + t4 * 2;
            float* dG = accG[mt][q];
            float* dU = accU[mt][q];
            if (R0 < m_end) {
                float a0 = dG[0] / (1.f + expf(-dG[0])) * dU[0];
                float a1 = dG[1] / (1.f + expf(-dG[1])) * dU[1];
                *(float2*)&g_act[(size_t)R0 * IDIM + col] = make_float2(a0, a1);
            }
            if (R1 < m_end) {
                float a2 = dG[2] / (1.f + expf(-dG[2])) * dU[2];
                float a3 = dG[3] / (1.f + expf(-dG[3])) * dU[3];
                *(float2*)&g_act[(size_t)R1 * IDIM + col] = make_float2(a2, a3);
            }
        }
    }
}

// ---------------- GEMM2: out[tok] += w * (A[slot] @ W2[e]) ----------------
// block 128m x 128n; 8 warps = 4m x 2n; warp m32 x n64
// grid: (32 m-tiles, HDIM/128 = 16 n-tiles, NE)
__global__ __launch_bounds__(256) void k_gemm2(const float* __restrict__ W2,
                                               float* __restrict__ out) {
    int e = blockIdx.z;
    int m_beg = g_off[e], m_end = g_off[e + 1];
    int m0 = m_beg + blockIdx.x * TM;
    if (m0 >= m_end) return;
    int n0 = blockIdx.y * 128;

    extern __shared__ __align__(16) float smem[];
    float* bufA[2] = { smem,            smem + STAGE_FLOATS };
    float* bufB[2] = { smem + A_FLOATS, smem + STAGE_FLOATS + A_FLOATS };

    __shared__ int   stok[TM];
    __shared__ float swt[TM];

    int tid = threadIdx.x, warp = tid >> 5, lane = tid & 31;
    int wm = warp >> 1, wn = warp & 1;
    int g = lane >> 2, t4 = lane & 3;

    if (tid < TM) {
        int gr = m0 + tid;
        bool v = (gr < m_end);
        stok[tid] = v ? g_slot_tok[gr] : 0;
        swt[tid]  = v ? g_slot_w[gr]   : 0.f;
    }
    __syncthreads();

    int ar = tid >> 1, ah = tid & 1;
    int arow = (m0 + ar < m_end) ? (m0 + ar) : m_beg;   // safe clamp (masked later)
    const float* aptr = g_act + (size_t)arow * IDIM + ah * 16;
    int sAoff = ar * SA + ah * 16;

    int bk = tid >> 3, bg = tid & 7;
    const float* bptr = W2 + (size_t)e * IDIM * HDIM + (size_t)bk * HDIM + n0 + bg * 16;
    int sBoff = bk * SB + bg * 16;
    const size_t bstride = (size_t)KC * HDIM;

    float acc[2][8][4];
#pragma unroll
    for (int mt = 0; mt < 2; mt++)
#pragma unroll
        for (int q = 0; q < 8; q++)
#pragma unroll
            for (int x = 0; x < 4; x++) acc[mt][q][x] = 0.f;

    float4 sa[4], sb[4];

    // ---- prologue ----
#pragma unroll
    for (int j = 0; j < 4; j++) {
        sa[j] = *(const float4*)(aptr + 4 * j);
        sb[j] = *(const float4*)(bptr + 4 * j);
    }
#pragma unroll
    for (int j = 0; j < 4; j++) {
        *(uint4*)(bufA[0] + sAoff + 4 * j) = cvt4(sa[j]);
        *(uint4*)(bufB[0] + sBoff + 4 * j) = cvt4(sb[j]);
    }
    __syncthreads();

    const int NI = IDIM / KC;   // 128
    for (int kc = 0; kc < NI; kc++) {
        int cur = kc & 1;
        bool more = (kc + 1 < NI);
        if (more) {
            const float* ap = aptr + (kc + 1) * KC;
            const float* bp = bptr + (size_t)(kc + 1) * bstride;
#pragma unroll
            for (int j = 0; j < 4; j++) {
                sa[j] = *(const float4*)(ap + 4 * j);
                sb[j] = *(const float4*)(bp + 4 * j);
            }
        }

        const float* cA = bufA[cur];
        const float* cB = bufB[cur];
#pragma unroll
        for (int ks = 0; ks < 4; ks++) {
            int k = ks * 8;
            unsigned af[2][4];
#pragma unroll
            for (int mt = 0; mt < 2; mt++) {
                int r0 = (wm * 32 + mt * 16 + g) * SA + k + t4;
                af[mt][0] = *(const unsigned*)(cA + r0);
                af[mt][1] = *(const unsigned*)(cA + r0 + 8 * SA);
                af[mt][2] = *(const unsigned*)(cA + r0 + 4);
                af[mt][3] = *(const unsigned*)(cA + r0 + 8 * SA + 4);
            }
#pragma unroll
            for (int q = 0; q < 8; q++) {
                int cb = wn * 64 + q * 8 + g;
                unsigned bf[2];
                bf[0] = *(const unsigned*)(cB + (k + t4) * SB + cb);
                bf[1] = *(const unsigned*)(cB + (k + t4 + 4) * SB + cb);
#pragma unroll
                for (int mt = 0; mt < 2; mt++)
                    mma8(acc[mt][q], af[mt], bf);
            }
        }

        if (more) {
            int nxt = cur ^ 1;
#pragma unroll
            for (int j = 0; j < 4; j++) {
                *(uint4*)(bufA[nxt] + sAoff + 4 * j) = cvt4(sa[j]);
                *(uint4*)(bufB[nxt] + sBoff + 4 * j) = cvt4(sb[j]);
            }
        }
        __syncthreads();
    }

    // ---- epilogue: weighted atomic scatter into out ----
#pragma unroll
    for (int mt = 0; mt < 2; mt++) {
        int L0 = wm * 32 + mt * 16 + g;
        int L1 = L0 + 8;
        bool v0 = (m0 + L0 < m_end);
        bool v1 = (m0 + L1 < m_end);
        int   tk0 = stok[L0], tk1 = stok[L1];
        float w0 = swt[L0],  w1 = swt[L1];
#pragma unroll
        for (int q = 0; q < 8; q++) {
            int col = n0 + wn * 64 + q * 8 + t4 * 2;
            float* d = acc[mt][q];
            if (v0) {
                atomicAdd(&out[(size_t)tk0 * HDIM + col],     w0 * d[0]);
                atomicAdd(&out[(size_t)tk0 * HDIM + col + 1], w0 * d[1]);
            }
            if (v1) {
                atomicAdd(&out[(size_t)tk1 * HDIM + col],     w1 * d[2]);
                atomicAdd(&out[(size_t)tk1 * HDIM + col + 1], w1 * d[3]);
            }
        }
    }
}

// ---------------- launch ----------------
extern "C" void kernel_launch(void* const* d_in, const int* in_sizes, int n_in,
                              void* d_out, int out_size) {
    const float* X      = (const float*)d_in[0];
    const float* logits = (const float*)d_in[1];
    const float* W13    = (const float*)d_in[2];
    const float* W2     = (const float*)d_in[3];
    float* out = (float*)d_out;

    static bool attr_done = false;
    if (!attr_done) {
        cudaFuncSetAttribute(k_gemm1, cudaFuncAttributeMaxDynamicSharedMemorySize, SMEM_BYTES);
        cudaFuncSetAttribute(k_gemm2, cudaFuncAttributeMaxDynamicSharedMemorySize, SMEM_BYTES);
        attr_done = true;
    }

    int n_out = T_TOK * HDIM;
    k_init<<<(n_out + 1023) / 1024, 1024>>>(out, n_out);
    k_route<<<(T_TOK + 255) / 256, 256>>>(logits);
    k_scan<<<1, 1>>>();
    k_scatter<<<(T_TOK + 255) / 256, 256>>>();

    k_gemm1<<<dim3(32, IDIM / 64, NE), 256, SMEM_BYTES>>>(X, W13);
    k_gemm2<<<dim3(32, HDIM / 128, NE), 256, SMEM_BYTES>>>(W2, out);
}

// round 9
// speedup vs baseline: 2.2703x; 1.0350x over previous
#include <cuda_runtime.h>
#include <cstdint>
#include <cmath>

#define T_TOK 4096
#define NE    8
#define HDIM  2048
#define IDIM  4096
#define TOPK  2
#define NSLOT (T_TOK * TOPK)

#define TM    128
#define KC    32
#define SA    36            // A smem row stride (floats): banks 4g+t4 -> conflict-free
#define SB    136           // B smem row stride (floats): banks 8k+g -> conflict-free

#define A_FLOATS (TM * SA)          // 4608
#define B_FLOATS (KC * SB)          // 4352
#define STAGE_FLOATS (A_FLOATS + B_FLOATS)
#define SMEM_BYTES (2 * STAGE_FLOATS * 4)   // 71680 -> 2 CTAs/SM = 143360 < 228KB

// ---------------- scratch (static device memory; no allocations) ----------------
__device__ float g_act[(size_t)NSLOT * IDIM];   // 128 MB activation scratch
__device__ int   g_counts[NE];
__device__ int   g_pos[NE];
__device__ int   g_off[NE + 1];
__device__ int   g_tok_e[T_TOK * TOPK];
__device__ float g_tok_w[T_TOK * TOPK];
__device__ int   g_slot_tok[NSLOT];
__device__ float g_slot_w[NSLOT];

// ---------------- helpers ----------------
__device__ __forceinline__ unsigned f2tf(float x) {
    unsigned r;
    asm("cvt.rna.tf32.f32 %0, %1;" : "=r"(r) : "f"(x));
    return r;
}
__device__ __forceinline__ uint4 cvt4(float4 v) {
    uint4 r;
    r.x = f2tf(v.x); r.y = f2tf(v.y); r.z = f2tf(v.z); r.w = f2tf(v.w);
    return r;
}
__device__ __forceinline__ void mma8(float* d, const unsigned* a, const unsigned* b) {
    asm volatile(
        "mma.sync.aligned.m16n8k8.row.col.f32.tf32.tf32.f32 "
        "{%0,%1,%2,%3}, {%4,%5,%6,%7}, {%8,%9}, {%0,%1,%2,%3};"
        : "+f"(d[0]), "+f"(d[1]), "+f"(d[2]), "+f"(d[3])
        : "r"(a[0]), "r"(a[1]), "r"(a[2]), "r"(a[3]), "r"(b[0]), "r"(b[1]));
}

// ---------------- small kernels ----------------
__global__ void k_init(float* __restrict__ out, int n) {
    int i = blockIdx.x * blockDim.x + threadIdx.x;
    if (i < n) out[i] = 0.f;
    if (i < NE) { g_counts[i] = 0; g_pos[i] = 0; }
}

__global__ void k_route(const float* __restrict__ logits) {
    int t = blockIdx.x * blockDim.x + threadIdx.x;
    if (t >= T_TOK) return;
    float p[NE];
    float mx = -1e30f;
#pragma unroll
    for (int e = 0; e < NE; e++) { p[e] = logits[t * NE + e]; mx = fmaxf(mx, p[e]); }
#pragma unroll
    for (int e = 0; e < NE; e++) p[e] = expf(p[e] - mx);
    int i0 = 0;
#pragma unroll
    for (int e = 1; e < NE; e++) if (p[e] > p[i0]) i0 = e;
    int i1 = (i0 == 0) ? 1 : 0;
#pragma unroll
    for (int e = 0; e < NE; e++) if (e != i0 && p[e] > p[i1]) i1 = e;
    float w0 = p[i0], w1 = p[i1];
    float s = w0 + w1;
    w0 /= s; w1 /= s;
    g_tok_e[t * 2] = i0;  g_tok_e[t * 2 + 1] = i1;
    g_tok_w[t * 2] = w0;  g_tok_w[t * 2 + 1] = w1;
    atomicAdd(&g_counts[i0], 1);
    atomicAdd(&g_counts[i1], 1);
}

__global__ void k_scan() {
    int acc = 0;
    for (int e = 0; e < NE; e++) { g_off[e] = acc; acc += g_counts[e]; }
    g_off[NE] = acc;
}

__global__ void k_scatter() {
    int t = blockIdx.x * blockDim.x + threadIdx.x;
    if (t >= T_TOK) return;
#pragma unroll
    for (int j = 0; j < TOPK; j++) {
        int e = g_tok_e[t * 2 + j];
        int pos = atomicAdd(&g_pos[e], 1);
        int s = g_off[e] + pos;
        g_slot_tok[s] = t;
        g_slot_w[s]   = g_tok_w[t * 2 + j];
    }
}

// ---------------- GEMM1: A[slot, n0:n0+64] = silu(Xg@W1)*(Xg@W3) ----------------
// block 128m x (64 gate + 64 up) B-cols; 8 warps = 4m x 2n; warp m32 x (32g+32u)
// grid: (32 m-tiles, IDIM/64 = 64 n-tiles, NE); 2 CTAs/SM
__global__ __launch_bounds__(256, 2) void k_gemm1(const float* __restrict__ X,
                                                  const float* __restrict__ W13) {
    int e = blockIdx.z;
    int m_beg = g_off[e], m_end = g_off[e + 1];
    int m0 = m_beg + blockIdx.x * TM;
    if (m0 >= m_end) return;
    int n0 = blockIdx.y * 64;

    extern __shared__ __align__(16) float smem[];
    float* bufA[2] = { smem,                 smem + STAGE_FLOATS };
    float* bufB[2] = { smem + A_FLOATS,      smem + STAGE_FLOATS + A_FLOATS };

    __shared__ int stok[TM];

    int tid = threadIdx.x, warp = tid >> 5, lane = tid & 31;
    int wm = warp >> 1, wn = warp & 1;
    int g = lane >> 2, t4 = lane & 3;

    if (tid < TM) {
        int gr = m0 + tid;
        stok[tid] = (gr < m_end) ? g_slot_tok[gr] : -1;
    }
    __syncthreads();

    // staging addressing
    int ar = tid >> 1, ah = tid & 1;                  // A: row 0..127, half 0/1
    int tok = stok[ar];
    const float* aptr = X + (size_t)(tok < 0 ? 0 : tok) * HDIM + ah * 16;
    int sAoff = ar * SA + ah * 16;

    int bk = tid >> 3, bg = tid & 7;                  // B: k-row 0..31, 16-col group
    const float* wbase = W13 + (size_t)e * HDIM * (2 * IDIM);
    int ncol = (bg < 4) ? (n0 + bg * 16) : (IDIM + n0 + (bg - 4) * 16);
    const float* bptr = wbase + (size_t)bk * (2 * IDIM) + ncol;
    int sBoff = bk * SB + bg * 16;
    const size_t bstride = (size_t)KC * (2 * IDIM);   // advance 32 k-rows

    float accG[2][4][4], accU[2][4][4];
#pragma unroll
    for (int mt = 0; mt < 2; mt++)
#pragma unroll
        for (int q = 0; q < 4; q++)
#pragma unroll
            for (int x = 0; x < 4; x++) { accG[mt][q][x] = 0.f; accU[mt][q][x] = 0.f; }

    float4 sa[4], sb[4];

    // ---- prologue: stage 0 ----
#pragma unroll
    for (int j = 0; j < 4; j++) {
        sa[j] = *(const float4*)(aptr + 4 * j);
        sb[j] = *(const float4*)(bptr + 4 * j);
    }
#pragma unroll
    for (int j = 0; j < 4; j++) {
        *(uint4*)(bufA[0] + sAoff + 4 * j) = cvt4(sa[j]);
        *(uint4*)(bufB[0] + sBoff + 4 * j) = cvt4(sb[j]);
    }
    __syncthreads();

    const int NI = HDIM / KC;   // 64
    for (int kc = 0; kc < NI; kc++) {
        int cur = kc & 1;
        bool more = (kc + 1 < NI);
        if (more) {
            const float* ap = aptr + (kc + 1) * KC;
            const float* bp = bptr + (size_t)(kc + 1) * bstride;
#pragma unroll
            for (int j = 0; j < 4; j++) {
                sa[j] = *(const float4*)(ap + 4 * j);
                sb[j] = *(const float4*)(bp + 4 * j);
            }
        }

        const float* cA = bufA[cur];
        const float* cB = bufB[cur];
#pragma unroll
        for (int ks = 0; ks < 4; ks++) {
            int k = ks * 8;
            unsigned af[2][4];
#pragma unroll
            for (int mt = 0; mt < 2; mt++) {
                int r0 = (wm * 32 + mt * 16 + g) * SA + k + t4;
                af[mt][0] = *(const unsigned*)(cA + r0);
                af[mt][1] = *(const unsigned*)(cA + r0 + 8 * SA);
                af[mt][2] = *(const unsigned*)(cA + r0 + 4);
                af[mt][3] = *(const unsigned*)(cA + r0 + 8 * SA + 4);
            }
#pragma unroll
            for (int q = 0; q < 4; q++) {
                // gate frag (smem cols 32*wn + 8q), up frag (cols 64 + 32*wn + 8q)
                int cbg = wn * 32 + q * 8 + g;
                int cbu = 64 + wn * 32 + q * 8 + g;
                unsigned bgf[2], buf_[2];
                bgf[0]  = *(const unsigned*)(cB + (k + t4) * SB + cbg);
                bgf[1]  = *(const unsigned*)(cB + (k + t4 + 4) * SB + cbg);
                buf_[0] = *(const unsigned*)(cB + (k + t4) * SB + cbu);
                buf_[1] = *(const unsigned*)(cB + (k + t4 + 4) * SB + cbu);
#pragma unroll
                for (int mt = 0; mt < 2; mt++) {
                    mma8(accG[mt][q], af[mt], bgf);
                    mma8(accU[mt][q], af[mt], buf_);
                }
            }
        }

        if (more) {
            int nxt = cur ^ 1;
#pragma unroll
            for (int j = 0; j < 4; j++) {
                *(uint4*)(bufA[nxt] + sAoff + 4 * j) = cvt4(sa[j]);
                *(uint4*)(bufB[nxt] + sBoff + 4 * j) = cvt4(sb[j]);
            }
        }
        __syncthreads();
    }

    // ---- epilogue: silu(gate)*up -> g_act (float2 stores, coalesced) ----
#pragma unroll
    for (int mt = 0; mt < 2; mt++) {
        int R0 = m0 + wm * 32 + mt * 16 + g;
        int R1 = R0 + 8;
#pragma unroll
        for (int q = 0; q < 4; q++) {
            int col = n0 + wn * 32 + q * 8 + t4 * 2;
            float* dG = accG[mt][q];
            float* dU = accU[mt][q];
            if (R0 < m_end) {
                float a0 = dG[0] / (1.f + expf(-dG[0])) * dU[0];
                float a1 = dG[1] / (1.f + expf(-dG[1])) * dU[1];
                *(float2*)&g_act[(size_t)R0 * IDIM + col] = make_float2(a0, a1);
            }
            if (R1 < m_end) {
                float a2 = dG[2] / (1.f + expf(-dG[2])) * dU[2];
                float a3 = dG[3] / (1.f + expf(-dG[3])) * dU[3];
                *(float2*)&g_act[(size_t)R1 * IDIM + col] = make_float2(a2, a3);
            }
        }
    }
}

// ---------------- GEMM2: out[tok] += w * (A[slot] @ W2[e]) ----------------
// block 128m x 128n; 8 warps = 4m x 2n; warp m32 x n64
// grid: (32 m-tiles, HDIM/128 = 16 n-tiles, NE); 2 CTAs/SM
__global__ __launch_bounds__(256, 2) void k_gemm2(const float* __restrict__ W2,
                                                  float* __restrict__ out) {
    int e = blockIdx.z;
    int m_beg = g_off[e], m_end = g_off[e + 1];
    int m0 = m_beg + blockIdx.x * TM;
    if (m0 >= m_end) return;
    int n0 = blockIdx.y * 128;

    extern __shared__ __align__(16) float smem[];
    float* bufA[2] = { smem,            smem + STAGE_FLOATS };
    float* bufB[2] = { smem + A_FLOATS, smem + STAGE_FLOATS + A_FLOATS };

    __shared__ int   stok[TM];
    __shared__ float swt[TM];

    int tid = threadIdx.x, warp = tid >> 5, lane = tid & 31;
    int wm = warp >> 1, wn = warp & 1;
    int g = lane >> 2, t4 = lane & 3;

    if (tid < TM) {
        int gr = m0 + tid;
        bool v = (gr < m_end);
        stok[tid] = v ? g_slot_tok[gr] : 0;
        swt[tid]  = v ? g_slot_w[gr]   : 0.f;
    }
    __syncthreads();

    int ar = tid >> 1, ah = tid & 1;
    int arow = (m0 + ar < m_end) ? (m0 + ar) : m_beg;   // safe clamp (masked later)
    const float* aptr = g_act + (size_t)arow * IDIM + ah * 16;
    int sAoff = ar * SA + ah * 16;

    int bk = tid >> 3, bg = tid & 7;
    const float* bptr = W2 + (size_t)e * IDIM * HDIM + (size_t)bk * HDIM + n0 + bg * 16;
    int sBoff = bk * SB + bg * 16;
    const size_t bstride = (size_t)KC * HDIM;

    float acc[2][8][4];
#pragma unroll
    for (int mt = 0; mt < 2; mt++)
#pragma unroll
        for (int q = 0; q < 8; q++)
#pragma unroll
            for (int x = 0; x < 4; x++) acc[mt][q][x] = 0.f;

    float4 sa[4], sb[4];

    // ---- prologue ----
#pragma unroll
    for (int j = 0; j < 4; j++) {
        sa[j] = *(const float4*)(aptr + 4 * j);
        sb[j] = *(const float4*)(bptr + 4 * j);
    }
#pragma unroll
    for (int j = 0; j < 4; j++) {
        *(uint4*)(bufA[0] + sAoff + 4 * j) = cvt4(sa[j]);
        *(uint4*)(bufB[0] + sBoff + 4 * j) = cvt4(sb[j]);
    }
    __syncthreads();

    const int NI = IDIM / KC;   // 128
    for (int kc = 0; kc < NI; kc++) {
        int cur = kc & 1;
        bool more = (kc + 1 < NI);
        if (more) {
            const float* ap = aptr + (kc + 1) * KC;
            const float* bp = bptr + (size_t)(kc + 1) * bstride;
#pragma unroll
            for (int j = 0; j < 4; j++) {
                sa[j] = *(const float4*)(ap + 4 * j);
                sb[j] = *(const float4*)(bp + 4 * j);
            }
        }

        const float* cA = bufA[cur];
        const float* cB = bufB[cur];
#pragma unroll
        for (int ks = 0; ks < 4; ks++) {
            int k = ks * 8;
            unsigned af[2][4];
#pragma unroll
            for (int mt = 0; mt < 2; mt++) {
                int r0 = (wm * 32 + mt * 16 + g) * SA + k + t4;
                af[mt][0] = *(const unsigned*)(cA + r0);
                af[mt][1] = *(const unsigned*)(cA + r0 + 8 * SA);
                af[mt][2] = *(const unsigned*)(cA + r0 + 4);
                af[mt][3] = *(const unsigned*)(cA + r0 + 8 * SA + 4);
            }
#pragma unroll
            for (int q = 0; q < 8; q++) {
                int cb = wn * 64 + q * 8 + g;
                unsigned bf[2];
                bf[0] = *(const unsigned*)(cB + (k + t4) * SB + cb);
                bf[1] = *(const unsigned*)(cB + (k + t4 + 4) * SB + cb);
#pragma unroll
                for (int mt = 0; mt < 2; mt++)
                    mma8(acc[mt][q], af[mt], bf);
            }
        }

        if (more) {
            int nxt = cur ^ 1;
#pragma unroll
            for (int j = 0; j < 4; j++) {
                *(uint4*)(bufA[nxt] + sAoff + 4 * j) = cvt4(sa[j]);
                *(uint4*)(bufB[nxt] + sBoff + 4 * j) = cvt4(sb[j]);
            }
        }
        __syncthreads();
    }

    // ---- epilogue: weighted atomic scatter into out ----
#pragma unroll
    for (int mt = 0; mt < 2; mt++) {
        int L0 = wm * 32 + mt * 16 + g;
        int L1 = L0 + 8;
        bool v0 = (m0 + L0 < m_end);
        bool v1 = (m0 + L1 < m_end);
        int   tk0 = stok[L0], tk1 = stok[L1];
        float w0 = swt[L0],  w1 = swt[L1];
#pragma unroll
        for (int q = 0; q < 8; q++) {
            int col = n0 + wn * 64 + q * 8 + t4 * 2;
            float* d = acc[mt][q];
            if (v0) {
                atomicAdd(&out[(size_t)tk0 * HDIM + col],     w0 * d[0]);
                atomicAdd(&out[(size_t)tk0 * HDIM + col + 1], w0 * d[1]);
            }
            if (v1) {
                atomicAdd(&out[(size_t)tk1 * HDIM + col],     w1 * d[2]);
                atomicAdd(&out[(size_t)tk1 * HDIM + col + 1], w1 * d[3]);
            }
        }
    }
}

// ---------------- launch ----------------
extern "C" void kernel_launch(void* const* d_in, const int* in_sizes, int n_in,
                              void* d_out, int out_size) {
    const float* X      = (const float*)d_in[0];
    const float* logits = (const float*)d_in[1];
    const float* W13    = (const float*)d_in[2];
    const float* W2     = (const float*)d_in[3];
    float* out = (float*)d_out;

    static bool attr_done = false;
    if (!attr_done) {
        cudaFuncSetAttribute(k_gemm1, cudaFuncAttributeMaxDynamicSharedMemorySize, SMEM_BYTES);
        cudaFuncSetAttribute(k_gemm2, cudaFuncAttributeMaxDynamicSharedMemorySize, SMEM_BYTES);
        attr_done = true;
    }

    int n_out = T_TOK * HDIM;
    k_init<<<(n_out + 1023) / 1024, 1024>>>(out, n_out);
    k_route<<<(T_TOK + 255) / 256, 256>>>(logits);
    k_scan<<<1, 1>>>();
    k_scatter<<<(T_TOK + 255) / 256, 256>>>();

    k_gemm1<<<dim3(32, IDIM / 64, NE), 256, SMEM_BYTES>>>(X, W13);
    k_gemm2<<<dim3(32, HDIM / 128, NE), 256, SMEM_BYTES>>>(W2, out);
}

// round 10
// speedup vs baseline: 3.6364x; 1.6017x over previous
#include <cuda_runtime.h>
#include <cuda_fp16.h>
#include <cstdint>
#include <cmath>

#define T_TOK 4096
#define NE    8
#define HDIM  2048
#define IDIM  4096
#define TOPK  2
#define NSLOT (T_TOK * TOPK)

#define TM    128
#define KC    32
#define SAH   20    // A smem row stride in uint(half2); bank m*20+t4 all-distinct mod 32
#define SBH   136   // B smem kh-row stride in uint(half2); bank t4*8+g all-distinct

#define A_UINTS (TM * SAH)            // 2560
#define B_UINTS ((KC / 2) * SBH)      // 2176
#define STAGE_UINTS (A_UINTS + B_UINTS)
#define SMEM_BYTES (2 * STAGE_UINTS * 4)   // 37888; 2 CTAs/SM = 75776 < 228KB

// ---------------- scratch (static device memory; no allocations) ----------------
__device__ float g_act[(size_t)NSLOT * IDIM];   // 128 MB activation scratch
__device__ int   g_counts[NE];
__device__ int   g_pos[NE];
__device__ int   g_off[NE + 1];
__device__ int   g_tok_e[T_TOK * TOPK];
__device__ float g_tok_w[T_TOK * TOPK];
__device__ int   g_slot_tok[NSLOT];
__device__ float g_slot_w[NSLOT];

// ---------------- helpers ----------------
__device__ __forceinline__ unsigned h2(float a, float b) {
    __half2 h = __floats2half2_rn(a, b);
    return *(unsigned*)&h;
}
// pack 16 consecutive-k fp32 (4 float4) into 2 uint4 of half2 (k-pairs)
__device__ __forceinline__ uint4 packA(float4 f0, float4 f1) {
    return make_uint4(h2(f0.x, f0.y), h2(f0.z, f0.w), h2(f1.x, f1.y), h2(f1.z, f1.w));
}
// interleave two k-rows (4 n each) into 4 half2 {k_even, k_odd}
__device__ __forceinline__ uint4 packB(float4 r0, float4 r1) {
    return make_uint4(h2(r0.x, r1.x), h2(r0.y, r1.y), h2(r0.z, r1.z), h2(r0.w, r1.w));
}
__device__ __forceinline__ void mma16(float* d, const unsigned* a, const unsigned* b) {
    asm volatile(
        "mma.sync.aligned.m16n8k16.row.col.f32.f16.f16.f32 "
        "{%0,%1,%2,%3}, {%4,%5,%6,%7}, {%8,%9}, {%0,%1,%2,%3};"
        : "+f"(d[0]), "+f"(d[1]), "+f"(d[2]), "+f"(d[3])
        : "r"(a[0]), "r"(a[1]), "r"(a[2]), "r"(a[3]), "r"(b[0]), "r"(b[1]));
}

// ---------------- small kernels ----------------
__global__ void k_init(float* __restrict__ out, int n) {
    int i = blockIdx.x * blockDim.x + threadIdx.x;
    if (i < n) out[i] = 0.f;
    if (i < NE) { g_counts[i] = 0; g_pos[i] = 0; }
}

__global__ void k_route(const float* __restrict__ logits) {
    int t = blockIdx.x * blockDim.x + threadIdx.x;
    if (t >= T_TOK) return;
    float p[NE];
    float mx = -1e30f;
#pragma unroll
    for (int e = 0; e < NE; e++) { p[e] = logits[t * NE + e]; mx = fmaxf(mx, p[e]); }
#pragma unroll
    for (int e = 0; e < NE; e++) p[e] = expf(p[e] - mx);
    int i0 = 0;
#pragma unroll
    for (int e = 1; e < NE; e++) if (p[e] > p[i0]) i0 = e;
    int i1 = (i0 == 0) ? 1 : 0;
#pragma unroll
    for (int e = 0; e < NE; e++) if (e != i0 && p[e] > p[i1]) i1 = e;
    float w0 = p[i0], w1 = p[i1];
    float s = w0 + w1;
    w0 /= s; w1 /= s;
    g_tok_e[t * 2] = i0;  g_tok_e[t * 2 + 1] = i1;
    g_tok_w[t * 2] = w0;  g_tok_w[t * 2 + 1] = w1;
    atomicAdd(&g_counts[i0], 1);
    atomicAdd(&g_counts[i1], 1);
}

__global__ void k_scan() {
    int acc = 0;
    for (int e = 0; e < NE; e++) { g_off[e] = acc; acc += g_counts[e]; }
    g_off[NE] = acc;
}

__global__ void k_scatter() {
    int t = blockIdx.x * blockDim.x + threadIdx.x;
    if (t >= T_TOK) return;
#pragma unroll
    for (int j = 0; j < TOPK; j++) {
        int e = g_tok_e[t * 2 + j];
        int pos = atomicAdd(&g_pos[e], 1);
        int s = g_off[e] + pos;
        g_slot_tok[s] = t;
        g_slot_w[s]   = g_tok_w[t * 2 + j];
    }
}

// ---------------- GEMM1: A[slot, n0:n0+64] = silu(Xg@W1)*(Xg@W3) ----------------
// block 128m x (64 gate + 64 up); 8 warps = 4m x 2n; warp m32 x (32g+32u); fp16 mma k16
// grid: (32 m-tiles, IDIM/64 = 64 n-tiles, NE); 2 CTAs/SM
__global__ __launch_bounds__(256, 2) void k_gemm1(const float* __restrict__ X,
                                                  const float* __restrict__ W13) {
    int e = blockIdx.z;
    int m_beg = g_off[e], m_end = g_off[e + 1];
    int m0 = m_beg + blockIdx.x * TM;
    if (m0 >= m_end) return;
    int n0 = blockIdx.y * 64;

    extern __shared__ __align__(16) unsigned smem[];
    unsigned* bufA[2] = { smem,           smem + STAGE_UINTS };
    unsigned* bufB[2] = { smem + A_UINTS, smem + STAGE_UINTS + A_UINTS };

    __shared__ int stok[TM];

    int tid = threadIdx.x, warp = tid >> 5, lane = tid & 31;
    int wm = warp >> 1, wn = warp & 1;
    int g = lane >> 2, t4 = lane & 3;

    if (tid < TM) {
        int gr = m0 + tid;
        stok[tid] = (gr < m_end) ? g_slot_tok[gr] : -1;
    }
    __syncthreads();

    // A staging: thread -> row ar, k-half ah (16 k each)
    int ar = tid >> 1, ah = tid & 1;
    int tok = stok[ar];
    const float* aptr = X + (size_t)(tok < 0 ? 0 : tok) * HDIM + ah * 16;
    int sAoff = ar * SAH + ah * 8;

    // B staging: 2 units/thread; unit u: kh = u>>5 (0..15), nseg = u&31
    int kh0 = tid >> 5, nseg = tid & 31;          // u0 = tid  -> kh 0..7
    int kh1 = kh0 + 8;                             // u1 = tid+256 -> kh 8..15
    const float* wbase = W13 + (size_t)e * HDIM * (2 * IDIM);
    int ncol = (nseg < 16) ? (n0 + nseg * 4) : (IDIM + n0 + (nseg - 16) * 4);
    const float* bptr0 = wbase + (size_t)(2 * kh0) * (2 * IDIM) + ncol;
    const float* bptr1 = wbase + (size_t)(2 * kh1) * (2 * IDIM) + ncol;
    int sBoff0 = kh0 * SBH + nseg * 4;
    int sBoff1 = kh1 * SBH + nseg * 4;
    const size_t brow = 2 * IDIM;
    const size_t bstride = (size_t)KC * brow;

    float accG[2][4][4], accU[2][4][4];
#pragma unroll
    for (int mt = 0; mt < 2; mt++)
#pragma unroll
        for (int q = 0; q < 4; q++)
#pragma unroll
            for (int x = 0; x < 4; x++) { accG[mt][q][x] = 0.f; accU[mt][q][x] = 0.f; }

    float4 sa[4], sb[4];

    // ---- prologue: stage 0 ----
#pragma unroll
    for (int j = 0; j < 4; j++) sa[j] = *(const float4*)(aptr + 4 * j);
    sb[0] = *(const float4*)(bptr0);
    sb[1] = *(const float4*)(bptr0 + brow);
    sb[2] = *(const float4*)(bptr1);
    sb[3] = *(const float4*)(bptr1 + brow);
    *(uint4*)(bufA[0] + sAoff)     = packA(sa[0], sa[1]);
    *(uint4*)(bufA[0] + sAoff + 4) = packA(sa[2], sa[3]);
    *(uint4*)(bufB[0] + sBoff0) = packB(sb[0], sb[1]);
    *(uint4*)(bufB[0] + sBoff1) = packB(sb[2], sb[3]);
    __syncthreads();

    const int NI = HDIM / KC;   // 64
    for (int kc = 0; kc < NI; kc++) {
        int cur = kc & 1;
        bool more = (kc + 1 < NI);
        if (more) {
            const float* ap = aptr + (kc + 1) * KC;
            const float* bp0 = bptr0 + (size_t)(kc + 1) * bstride;
            const float* bp1 = bptr1 + (size_t)(kc + 1) * bstride;
#pragma unroll
            for (int j = 0; j < 4; j++) sa[j] = *(const float4*)(ap + 4 * j);
            sb[0] = *(const float4*)(bp0);
            sb[1] = *(const float4*)(bp0 + brow);
            sb[2] = *(const float4*)(bp1);
            sb[3] = *(const float4*)(bp1 + brow);
        }

        const unsigned* cA = bufA[cur];
        const unsigned* cB = bufB[cur];
#pragma unroll
        for (int ks = 0; ks < 2; ks++) {
            int khb = ks * 8;
            unsigned af[2][4];
#pragma unroll
            for (int mt = 0; mt < 2; mt++) {
                int r0 = (wm * 32 + mt * 16 + g) * SAH + khb + t4;
                af[mt][0] = cA[r0];
                af[mt][1] = cA[r0 + 8 * SAH];
                af[mt][2] = cA[r0 + 4];
                af[mt][3] = cA[r0 + 8 * SAH + 4];
            }
#pragma unroll
            for (int q = 0; q < 4; q++) {
                int cbg = wn * 32 + q * 8 + g;
                int cbu = 64 + wn * 32 + q * 8 + g;
                unsigned bgf[2], buf_[2];
                bgf[0]  = cB[(khb + t4) * SBH + cbg];
                bgf[1]  = cB[(khb + t4 + 4) * SBH + cbg];
                buf_[0] = cB[(khb + t4) * SBH + cbu];
                buf_[1] = cB[(khb + t4 + 4) * SBH + cbu];
#pragma unroll
                for (int mt = 0; mt < 2; mt++) {
                    mma16(accG[mt][q], af[mt], bgf);
                    mma16(accU[mt][q], af[mt], buf_);
                }
            }
        }

        if (more) {
            int nxt = cur ^ 1;
            *(uint4*)(bufA[nxt] + sAoff)     = packA(sa[0], sa[1]);
            *(uint4*)(bufA[nxt] + sAoff + 4) = packA(sa[2], sa[3]);
            *(uint4*)(bufB[nxt] + sBoff0) = packB(sb[0], sb[1]);
            *(uint4*)(bufB[nxt] + sBoff1) = packB(sb[2], sb[3]);
        }
        __syncthreads();
    }

    // ---- epilogue: silu(gate)*up -> g_act (float2 stores, coalesced) ----
#pragma unroll
    for (int mt = 0; mt < 2; mt++) {
        int R0 = m0 + wm * 32 + mt * 16 + g;
        int R1 = R0 + 8;
#pragma unroll
        for (int q = 0; q < 4; q++) {
            int col = n0 + wn * 32 + q * 8 + t4 * 2;
            float* dG = accG[mt][q];
            float* dU = accU[mt][q];
            if (R0 < m_end) {
                float a0 = dG[0] / (1.f + expf(-dG[0])) * dU[0];
                float a1 = dG[1] / (1.f + expf(-dG[1])) * dU[1];
                *(float2*)&g_act[(size_t)R0 * IDIM + col] = make_float2(a0, a1);
            }
            if (R1 < m_end) {
                float a2 = dG[2] / (1.f + expf(-dG[2])) * dU[2];
                float a3 = dG[3] / (1.f + expf(-dG[3])) * dU[3];
                *(float2*)&g_act[(size_t)R1 * IDIM + col] = make_float2(a2, a3);
            }
        }
    }
}

// ---------------- GEMM2: out[tok] += w * (A[slot] @ W2[e]) ----------------
// block 128m x 128n; 8 warps = 4m x 2n; warp m32 x n64; fp16 mma k16
// grid: (32 m-tiles, HDIM/128 = 16 n-tiles, NE); 2 CTAs/SM
__global__ __launch_bounds__(256, 2) void k_gemm2(const float* __restrict__ W2,
                                                  float* __restrict__ out) {
    int e = blockIdx.z;
    int m_beg = g_off[e], m_end = g_off[e + 1];
    int m0 = m_beg + blockIdx.x * TM;
    if (m0 >= m_end) return;
    int n0 = blockIdx.y * 128;

    extern __shared__ __align__(16) unsigned smem[];
    unsigned* bufA[2] = { smem,           smem + STAGE_UINTS };
    unsigned* bufB[2] = { smem + A_UINTS, smem + STAGE_UINTS + A_UINTS };

    __shared__ int   stok[TM];
    __shared__ float swt[TM];

    int tid = threadIdx.x, warp = tid >> 5, lane = tid & 31;
    int wm = warp >> 1, wn = warp & 1;
    int g = lane >> 2, t4 = lane & 3;

    if (tid < TM) {
        int gr = m0 + tid;
        bool v = (gr < m_end);
        stok[tid] = v ? g_slot_tok[gr] : 0;
        swt[tid]  = v ? g_slot_w[gr]   : 0.f;
    }
    __syncthreads();

    int ar = tid >> 1, ah = tid & 1;
    int arow = (m0 + ar < m_end) ? (m0 + ar) : m_beg;   // safe clamp (masked later)
    const float* aptr = g_act + (size_t)arow * IDIM + ah * 16;
    int sAoff = ar * SAH + ah * 8;

    int kh0 = tid >> 5, nseg = tid & 31;
    int kh1 = kh0 + 8;
    const float* wbase = W2 + (size_t)e * IDIM * HDIM;
    const float* bptr0 = wbase + (size_t)(2 * kh0) * HDIM + n0 + nseg * 4;
    const float* bptr1 = wbase + (size_t)(2 * kh1) * HDIM + n0 + nseg * 4;
    int sBoff0 = kh0 * SBH + nseg * 4;
    int sBoff1 = kh1 * SBH + nseg * 4;
    const size_t brow = HDIM;
    const size_t bstride = (size_t)KC * brow;

    float acc[2][8][4];
#pragma unroll
    for (int mt = 0; mt < 2; mt++)
#pragma unroll
        for (int q = 0; q < 8; q++)
#pragma unroll
            for (int x = 0; x < 4; x++) acc[mt][q][x] = 0.f;

    float4 sa[4], sb[4];

    // ---- prologue ----
#pragma unroll
    for (int j = 0; j < 4; j++) sa[j] = *(const float4*)(aptr + 4 * j);
    sb[0] = *(const float4*)(bptr0);
    sb[1] = *(const float4*)(bptr0 + brow);
    sb[2] = *(const float4*)(bptr1);
    sb[3] = *(const float4*)(bptr1 + brow);
    *(uint4*)(bufA[0] + sAoff)     = packA(sa[0], sa[1]);
    *(uint4*)(bufA[0] + sAoff + 4) = packA(sa[2], sa[3]);
    *(uint4*)(bufB[0] + sBoff0) = packB(sb[0], sb[1]);
    *(uint4*)(bufB[0] + sBoff1) = packB(sb[2], sb[3]);
    __syncthreads();

    const int NI = IDIM / KC;   // 128
    for (int kc = 0; kc < NI; kc++) {
        int cur = kc & 1;
        bool more = (kc + 1 < NI);
        if (more) {
            const float* ap = aptr + (kc + 1) * KC;
            const float* bp0 = bptr0 + (size_t)(kc + 1) * bstride;
            const float* bp1 = bptr1 + (size_t)(kc + 1) * bstride;
#pragma unroll
            for (int j = 0; j < 4; j++) sa[j] = *(const float4*)(ap + 4 * j);
            sb[0] = *(const float4*)(bp0);
            sb[1] = *(const float4*)(bp0 + brow);
            sb[2] = *(const float4*)(bp1);
            sb[3] = *(const float4*)(bp1 + brow);
        }

        const unsigned* cA = bufA[cur];
        const unsigned* cB = bufB[cur];
#pragma unroll
        for (int ks = 0; ks < 2; ks++) {
            int khb = ks * 8;
            unsigned af[2][4];
#pragma unroll
            for (int mt = 0; mt < 2; mt++) {
                int r0 = (wm * 32 + mt * 16 + g) * SAH + khb + t4;
                af[mt][0] = cA[r0];
                af[mt][1] = cA[r0 + 8 * SAH];
                af[mt][2] = cA[r0 + 4];
                af[mt][3] = cA[r0 + 8 * SAH + 4];
            }
#pragma unroll
            for (int q = 0; q < 8; q++) {
                int cb = wn * 64 + q * 8 + g;
                unsigned bf[2];
                bf[0] = cB[(khb + t4) * SBH + cb];
                bf[1] = cB[(khb + t4 + 4) * SBH + cb];
#pragma unroll
                for (int mt = 0; mt < 2; mt++)
                    mma16(acc[mt][q], af[mt], bf);
            }
        }

        if (more) {
            int nxt = cur ^ 1;
            *(uint4*)(bufA[nxt] + sAoff)     = packA(sa[0], sa[1]);
            *(uint4*)(bufA[nxt] + sAoff + 4) = packA(sa[2], sa[3]);
            *(uint4*)(bufB[nxt] + sBoff0) = packB(sb[0], sb[1]);
            *(uint4*)(bufB[nxt] + sBoff1) = packB(sb[2], sb[3]);
        }
        __syncthreads();
    }

    // ---- epilogue: weighted atomic scatter into out ----
#pragma unroll
    for (int mt = 0; mt < 2; mt++) {
        int L0 = wm * 32 + mt * 16 + g;
        int L1 = L0 + 8;
        bool v0 = (m0 + L0 < m_end);
        bool v1 = (m0 + L1 < m_end);
        int   tk0 = stok[L0], tk1 = stok[L1];
        float w0 = swt[L0],  w1 = swt[L1];
#pragma unroll
        for (int q = 0; q < 8; q++) {
            int col = n0 + wn * 64 + q * 8 + t4 * 2;
            float* d = acc[mt][q];
            if (v0) {
                atomicAdd(&out[(size_t)tk0 * HDIM + col],     w0 * d[0]);
                atomicAdd(&out[(size_t)tk0 * HDIM + col + 1], w0 * d[1]);
            }
            if (v1) {
                atomicAdd(&out[(size_t)tk1 * HDIM + col],     w1 * d[2]);
                atomicAdd(&out[(size_t)tk1 * HDIM + col + 1], w1 * d[3]);
            }
        }
    }
}

// ---------------- launch ----------------
extern "C" void kernel_launch(void* const* d_in, const int* in_sizes, int n_in,
                              void* d_out, int out_size) {
    const float* X      = (const float*)d_in[0];
    const float* logits = (const float*)d_in[1];
    const float* W13    = (const float*)d_in[2];
    const float* W2     = (const float*)d_in[3];
    float* out = (float*)d_out;

    static bool attr_done = false;
    if (!attr_done) {
        cudaFuncSetAttribute(k_gemm1, cudaFuncAttributeMaxDynamicSharedMemorySize, SMEM_BYTES);
        cudaFuncSetAttribute(k_gemm2, cudaFuncAttributeMaxDynamicSharedMemorySize, SMEM_BYTES);
        attr_done = true;
    }

    int n_out = T_TOK * HDIM;
    k_init<<<(n_out + 1023) / 1024, 1024>>>(out, n_out);
    k_route<<<(T_TOK + 255) / 256, 256>>>(logits);
    k_scan<<<1, 1>>>();
    k_scatter<<<(T_TOK + 255) / 256, 256>>>();

    k_gemm1<<<dim3(32, IDIM / 64, NE), 256, SMEM_BYTES>>>(X, W13);
    k_gemm2<<<dim3(32, HDIM / 128, NE), 256, SMEM_BYTES>>>(W2, out);
}

// round 12
// speedup vs baseline: 5.1381x; 1.4130x over previous
#include <cuda_runtime.h>
#include <cuda_fp16.h>
#include <cstdint>
#include <cmath>

#define T_TOK 4096
#define NE    8
#define HDIM  2048
#define IDIM  4096
#define TOPK  2
#define NSLOT (T_TOK * TOPK)

#define TM    128
#define KC    32
#define SAH   20     // A smem row stride (uints = half2); STS/LDS conflict-free
#define SBH   136    // B smem kh-row stride (uints); 8kh+g pattern conflict-free

#define A_UINTS (TM * SAH)        // 2560
#define B_UINTS (16 * SBH)        // 2176
#define STG     (A_UINTS + B_UINTS)
#define NSTAGE  3
#define SMEM_BYTES (NSTAGE * STG * 4)   // 56832; 2 CTAs/SM = 113664 < 228KB

// ---------------- scratch (static device memory; no allocations) ----------------
__device__ unsigned xh[(size_t)T_TOK * HDIM / 2];            // 16 MB  fp16 X, half2-packed
__device__ unsigned w13h[(size_t)NE * 1024 * 8192];          // 268 MB [e][kh][n] half2(k,k+1)
__device__ unsigned w2h[(size_t)NE * 2048 * 2048];           // 134 MB [e][kh][n]
__device__ unsigned acth[(size_t)NSLOT * IDIM / 2];          // 64 MB  fp16 activations
__device__ int   g_counts[NE];
__device__ int   g_pos[NE];
__device__ int   g_off[NE + 1];
__device__ int   g_tok_e[T_TOK * TOPK];
__device__ float g_tok_w[T_TOK * TOPK];
__device__ int   g_slot_tok[NSLOT];
__device__ float g_slot_w[NSLOT];

// ---------------- helpers ----------------
__device__ __forceinline__ unsigned h2(float a, float b) {
    __half2 h = __floats2half2_rn(a, b);
    return *(unsigned*)&h;
}
__device__ __forceinline__ void mma16(float* d, const unsigned* a, const unsigned* b) {
    asm volatile(
        "mma.sync.aligned.m16n8k16.row.col.f32.f16.f16.f32 "
        "{%0,%1,%2,%3}, {%4,%5,%6,%7}, {%8,%9}, {%0,%1,%2,%3};"
        : "+f"(d[0]), "+f"(d[1]), "+f"(d[2]), "+f"(d[3])
        : "r"(a[0]), "r"(a[1]), "r"(a[2]), "r"(a[3]), "r"(b[0]), "r"(b[1]));
}
__device__ __forceinline__ uint32_t s2u(const void* p) {
    uint32_t a;
    asm("{ .reg .u64 t; cvta.to.shared.u64 t, %1; cvt.u32.u64 %0, t; }" : "=r"(a) : "l"(p));
    return a;
}
__device__ __forceinline__ void cpa16(uint32_t dst, const void* src) {
    asm volatile("cp.async.cg.shared.global [%0], [%1], 16;" :: "r"(dst), "l"(src));
}
#define CP_COMMIT() asm volatile("cp.async.commit_group;" ::: "memory")
#define CP_WAIT1()  asm volatile("cp.async.wait_group 1;" ::: "memory")

// ---------------- small kernels ----------------
__global__ void k_init(float* __restrict__ out, int n) {
    int i = blockIdx.x * blockDim.x + threadIdx.x;
    if (i < n) out[i] = 0.f;
    if (i < NE) { g_counts[i] = 0; g_pos[i] = 0; }
}

__global__ void k_route(const float* __restrict__ logits) {
    int t = blockIdx.x * blockDim.x + threadIdx.x;
    if (t >= T_TOK) return;
    float p[NE];
    float mx = -1e30f;
#pragma unroll
    for (int e = 0; e < NE; e++) { p[e] = logits[t * NE + e]; mx = fmaxf(mx, p[e]); }
#pragma unroll
    for (int e = 0; e < NE; e++) p[e] = expf(p[e] - mx);
    int i0 = 0;
#pragma unroll
    for (int e = 1; e < NE; e++) if (p[e] > p[i0]) i0 = e;
    int i1 = (i0 == 0) ? 1 : 0;
#pragma unroll
    for (int e = 0; e < NE; e++) if (e != i0 && p[e] > p[i1]) i1 = e;
    float w0 = p[i0], w1 = p[i1];
    float s = w0 + w1;
    w0 /= s; w1 /= s;
    g_tok_e[t * 2] = i0;  g_tok_e[t * 2 + 1] = i1;
    g_tok_w[t * 2] = w0;  g_tok_w[t * 2 + 1] = w1;
    atomicAdd(&g_counts[i0], 1);
    atomicAdd(&g_counts[i1], 1);
}

__global__ void k_scan() {
    int acc = 0;
    for (int e = 0; e < NE; e++) { g_off[e] = acc; acc += g_counts[e]; }
    g_off[NE] = acc;
}

__global__ void k_scatter() {
    int t = blockIdx.x * blockDim.x + threadIdx.x;
    if (t >= T_TOK) return;
#pragma unroll
    for (int j = 0; j < TOPK; j++) {
        int e = g_tok_e[t * 2 + j];
        int pos = atomicAdd(&g_pos[e], 1);
        int s = g_off[e] + pos;
        g_slot_tok[s] = t;
        g_slot_w[s]   = g_tok_w[t * 2 + j];
    }
}

// ---------------- fp32 -> fp16 conversion kernels (one-time per launch) ----------------
__global__ void k_cvt_x(const float* __restrict__ X) {
    int i = blockIdx.x * blockDim.x + threadIdx.x;   // over T*H/4
    float4 v = *(const float4*)(X + 4 * (size_t)i);
    ((uint2*)xh)[i] = make_uint2(h2(v.x, v.y), h2(v.z, v.w));
}

// W13 [E][H][2I] -> w13h [e][kh=H/2][n=2I] half2(k, k+1); thread = 1 uint4 (4 n)
__global__ void k_cvt_w13(const float* __restrict__ W13) {
    int o = blockIdx.x * blockDim.x + threadIdx.x;   // NE*1024*2048
    int c = o & 2047;
    int row = o >> 11;
    int kh = row & 1023;
    int e = row >> 10;
    const float* s0 = W13 + ((size_t)e * 2048 + 2 * kh) * 8192 + 4 * c;
    float4 r0 = *(const float4*)s0;
    float4 r1 = *(const float4*)(s0 + 8192);
    ((uint4*)w13h)[o] = make_uint4(h2(r0.x, r1.x), h2(r0.y, r1.y), h2(r0.z, r1.z), h2(r0.w, r1.w));
}

// W2 [E][I][H] -> w2h [e][kh=I/2][n=H]
__global__ void k_cvt_w2(const float* __restrict__ W2) {
    int o = blockIdx.x * blockDim.x + threadIdx.x;   // NE*2048*512
    int c = o & 511;
    int row = o >> 9;
    int kh = row & 2047;
    int e = row >> 11;
    const float* s0 = W2 + ((size_t)e * 4096 + 2 * kh) * 2048 + 4 * c;
    float4 r0 = *(const float4*)s0;
    float4 r1 = *(const float4*)(s0 + 2048);
    ((uint4*)w2h)[o] = make_uint4(h2(r0.x, r1.x), h2(r0.y, r1.y), h2(r0.z, r1.z), h2(r0.w, r1.w));
}

// ---------------- GEMM1: acth[slot, n0:n0+64] = silu(X@W1)*(X@W3) ----------------
// 128 threads, 4 warps (2m x 2n), warp m64 x (32gate+32up); cp.async 3-stage; 2 CTAs/SM
// grid: (32 m-tiles, IDIM/64 = 64 n-tiles, NE)
__global__ __launch_bounds__(128, 2) void k_gemm1() {
    int e = blockIdx.z;
    int m_beg = g_off[e], m_end = g_off[e + 1];
    int m0 = m_beg + blockIdx.x * TM;
    if (m0 >= m_end) return;
    int n0 = blockIdx.y * 64;

    extern __shared__ __align__(16) unsigned smem[];
    __shared__ int stok[TM];

    int tid = threadIdx.x, warp = tid >> 5, lane = tid & 31;
    int wm = warp >> 1, wn = warp & 1;
    int g = lane >> 2, t4 = lane & 3;

    {
        int gr = m0 + tid;
        stok[tid] = (gr < m_end) ? g_slot_tok[gr] : -1;
    }
    __syncthreads();

    int tok = stok[tid];
    if (tok < 0) tok = stok[0];                       // valid row; garbage masked at epilogue
    const unsigned* asrc = xh + (size_t)tok * (HDIM / 2);
    int kh = (tid & 3) | ((tid >> 5) << 2);           // 0..15
    int c4 = (tid >> 2) & 7;                          // 0..7
    const unsigned* bsrc = w13h + ((size_t)e * 1024 + kh) * 8192 + n0;
    uint32_t smemu = s2u(smem);
    uint32_t aDst = smemu + (tid * SAH) * 4;
    uint32_t bDst = smemu + (A_UINTS + kh * SBH) * 4;

#define G1_ISSUE(kc_, s_) do {                                                  \
    uint32_t _o = (uint32_t)(s_) * (STG * 4);                                   \
    const unsigned* _a = asrc + (kc_) * 16;                                     \
    cpa16(aDst + _o,      _a);                                                  \
    cpa16(aDst + _o + 16, _a + 4);                                              \
    cpa16(aDst + _o + 32, _a + 8);                                              \
    cpa16(aDst + _o + 48, _a + 12);                                             \
    const unsigned* _w = bsrc + (size_t)(kc_) * (16 * 8192);                    \
    _Pragma("unroll")                                                           \
    for (int _j = 0; _j < 4; _j++) {                                            \
        int _p4 = c4 + 8 * _j;                                                  \
        int _nc = (_p4 < 16) ? 4 * _p4 : (IDIM - 64 + 4 * _p4);                 \
        cpa16(bDst + _o + 16 * _p4, _w + _nc);                                  \
    }                                                                           \
} while (0)

    float accG[4][4][4], accU[4][4][4];
#pragma unroll
    for (int mt = 0; mt < 4; mt++)
#pragma unroll
        for (int q = 0; q < 4; q++)
#pragma unroll
            for (int x = 0; x < 4; x++) { accG[mt][q][x] = 0.f; accU[mt][q][x] = 0.f; }

    const int NI = HDIM / KC;   // 64
    G1_ISSUE(0, 0); CP_COMMIT();
    G1_ISSUE(1, 1); CP_COMMIT();

    int sc = 0, si = 2;
    for (int kc = 0; kc < NI; kc++) {
        CP_WAIT1();
        __syncthreads();
        if (kc + 2 < NI) G1_ISSUE(kc + 2, si);
        CP_COMMIT();
        si = (si == 2) ? 0 : si + 1;

        const unsigned* cA = smem + sc * STG;
        const unsigned* cB = cA + A_UINTS;
        sc = (sc == 2) ? 0 : sc + 1;

#pragma unroll
        for (int ks = 0; ks < 2; ks++) {
            int khb = ks * 8;
            unsigned af[4][4];
#pragma unroll
            for (int mt = 0; mt < 4; mt++) {
                int r = (wm * 64 + mt * 16 + g) * SAH + khb + t4;
                af[mt][0] = cA[r];
                af[mt][1] = cA[r + 8 * SAH];
                af[mt][2] = cA[r + 4];
                af[mt][3] = cA[r + 8 * SAH + 4];
            }
            int rb0 = (khb + t4) * SBH, rb1 = (khb + t4 + 4) * SBH;
#pragma unroll
            for (int q = 0; q < 4; q++) {
                int cbg = wn * 32 + q * 8 + g;
                unsigned bg[2], bu[2];
                bg[0] = cB[rb0 + cbg];       bg[1] = cB[rb1 + cbg];
                bu[0] = cB[rb0 + cbg + 64];  bu[1] = cB[rb1 + cbg + 64];
#pragma unroll
                for (int mt = 0; mt < 4; mt++) {
                    mma16(accG[mt][q], af[mt], bg);
                    mma16(accU[mt][q], af[mt], bu);
                }
            }
        }
    }
#undef G1_ISSUE

    // epilogue: silu(gate)*up -> acth (half2 stores)
#pragma unroll
    for (int mt = 0; mt < 4; mt++) {
        int R0 = m0 + wm * 64 + mt * 16 + g;
        int R1 = R0 + 8;
#pragma unroll
        for (int q = 0; q < 4; q++) {
            int col = n0 + wn * 32 + q * 8 + t4 * 2;
            float* G = accG[mt][q];
            float* U = accU[mt][q];
            if (R0 < m_end) {
                float a0 = G[0] / (1.f + expf(-G[0])) * U[0];
                float a1 = G[1] / (1.f + expf(-G[1])) * U[1];
                ((__half2*)acth)[(size_t)R0 * (IDIM / 2) + (col >> 1)] = __floats2half2_rn(a0, a1);
            }
            if (R1 < m_end) {
                float a2 = G[2] / (1.f + expf(-G[2])) * U[2];
                float a3 = G[3] / (1.f + expf(-G[3])) * U[3];
                ((__half2*)acth)[(size_t)R1 * (IDIM / 2) + (col >> 1)] = __floats2half2_rn(a2, a3);
            }
        }
    }
}

// ---------------- GEMM2: out[tok] += w * (acth[slot] @ W2[e]) ----------------
// 128 threads, 4 warps (2m x 2n), warp m64 x n64; block 128x128; cp.async 3-stage
// grid: (32 m-tiles, HDIM/128 = 16 n-tiles, NE)
__global__ __launch_bounds__(128, 2) void k_gemm2(float* __restrict__ out) {
    int e = blockIdx.z;
    int m_beg = g_off[e], m_end = g_off[e + 1];
    int m0 = m_beg + blockIdx.x * TM;
    if (m0 >= m_end) return;
    int n0 = blockIdx.y * 128;

    extern __shared__ __align__(16) unsigned smem[];
    __shared__ int   stok[TM];
    __shared__ float swt[TM];

    int tid = threadIdx.x, warp = tid >> 5, lane = tid & 31;
    int wm = warp >> 1, wn = warp & 1;
    int g = lane >> 2, t4 = lane & 3;

    {
        int gr = m0 + tid;
        bool v = (gr < m_end);
        stok[tid] = v ? g_slot_tok[gr] : 0;
        swt[tid]  = v ? g_slot_w[gr]   : 0.f;
    }
    __syncthreads();

    int arow = (m0 + tid < m_end) ? (m0 + tid) : m0;
    const unsigned* asrc = acth + (size_t)arow * (IDIM / 2);
    int kh = (tid & 3) | ((tid >> 5) << 2);
    int c4 = (tid >> 2) & 7;
    const unsigned* bsrc = w2h + ((size_t)e * 2048 + kh) * 2048 + n0;
    uint32_t smemu = s2u(smem);
    uint32_t aDst = smemu + (tid * SAH) * 4;
    uint32_t bDst = smemu + (A_UINTS + kh * SBH) * 4;

#define G2_ISSUE(kc_, s_) do {                                                  \
    uint32_t _o = (uint32_t)(s_) * (STG * 4);                                   \
    const unsigned* _a = asrc + (kc_) * 16;                                     \
    cpa16(aDst + _o,      _a);                                                  \
    cpa16(aDst + _o + 16, _a + 4);                                              \
    cpa16(aDst + _o + 32, _a + 8);                                              \
    cpa16(aDst + _o + 48, _a + 12);                                             \
    const unsigned* _w = bsrc + (size_t)(kc_) * (16 * 2048);                    \
    _Pragma("unroll")                                                           \
    for (int _j = 0; _j < 4; _j++) {                                            \
        int _p4 = c4 + 8 * _j;                                                  \
        cpa16(bDst + _o + 16 * _p4, _w + 4 * _p4);                              \
    }                                                                           \
} while (0)

    float acc[4][8][4];
#pragma unroll
    for (int mt = 0; mt < 4; mt++)
#pragma unroll
        for (int q = 0; q < 8; q++)
#pragma unroll
            for (int x = 0; x < 4; x++) acc[mt][q][x] = 0.f;

    const int NI = IDIM / KC;   // 128
    G2_ISSUE(0, 0); CP_COMMIT();
    G2_ISSUE(1, 1); CP_COMMIT();

    int sc = 0, si = 2;
    for (int kc = 0; kc < NI; kc++) {
        CP_WAIT1();
        __syncthreads();
        if (kc + 2 < NI) G2_ISSUE(kc + 2, si);
        CP_COMMIT();
        si = (si == 2) ? 0 : si + 1;

        const unsigned* cA = smem + sc * STG;
        const unsigned* cB = cA + A_UINTS;
        sc = (sc == 2) ? 0 : sc + 1;

#pragma unroll
        for (int ks = 0; ks < 2; ks++) {
            int khb = ks * 8;
            unsigned af[4][4];
#pragma unroll
            for (int mt = 0; mt < 4; mt++) {
                int r = (wm * 64 + mt * 16 + g) * SAH + khb + t4;
                af[mt][0] = cA[r];
                af[mt][1] = cA[r + 8 * SAH];
                af[mt][2] = cA[r + 4];
                af[mt][3] = cA[r + 8 * SAH + 4];
            }
            int rb0 = (khb + t4) * SBH, rb1 = (khb + t4 + 4) * SBH;
#pragma unroll
            for (int q = 0; q < 8; q++) {
                int cb = wn * 64 + q * 8 + g;
                unsigned bf[2];
                bf[0] = cB[rb0 + cb];
                bf[1] = cB[rb1 + cb];
#pragma unroll
                for (int mt = 0; mt < 4; mt++)
                    mma16(acc[mt][q], af[mt], bf);
            }
        }
    }
#undef G2_ISSUE

    // epilogue: weighted atomic scatter into out
#pragma unroll
    for (int mt = 0; mt < 4; mt++) {
        int L0 = wm * 64 + mt * 16 + g;
        int L1 = L0 + 8;
        bool v0 = (m0 + L0 < m_end);
        bool v1 = (m0 + L1 < m_end);
        int   tk0 = stok[L0], tk1 = stok[L1];
        float w0 = swt[L0],  w1 = swt[L1];
#pragma unroll
        for (int q = 0; q < 8; q++) {
            int col = n0 + wn * 64 + q * 8 + t4 * 2;
            float* d = acc[mt][q];
            if (v0) {
                atomicAdd(&out[(size_t)tk0 * HDIM + col],     w0 * d[0]);
                atomicAdd(&out[(size_t)tk0 * HDIM + col + 1], w0 * d[1]);
            }
            if (v1) {
                atomicAdd(&out[(size_t)tk1 * HDIM + col],     w1 * d[2]);
                atomicAdd(&out[(size_t)tk1 * HDIM + col + 1], w1 * d[3]);
            }
        }
    }
}

// ---------------- launch ----------------
extern "C" void kernel_launch(void* const* d_in, const int* in_sizes, int n_in,
                              void* d_out, int out_size) {
    const float* X      = (const float*)d_in[0];
    const float* logits = (const float*)d_in[1];
    const float* W13    = (const float*)d_in[2];
    const float* W2     = (const float*)d_in[3];
    float* out = (float*)d_out;

    static bool attr_done = false;
    if (!attr_done) {
        cudaFuncSetAttribute(k_gemm1, cudaFuncAttributeMaxDynamicSharedMemorySize, SMEM_BYTES);
        cudaFuncSetAttribute(k_gemm2, cudaFuncAttributeMaxDynamicSharedMemorySize, SMEM_BYTES);
        attr_done = true;
    }

    int n_out = T_TOK * HDIM;
    k_init<<<(n_out + 1023) / 1024, 1024>>>(out, n_out);
    k_route<<<(T_TOK + 255) / 256, 256>>>(logits);
    k_scan<<<1, 1>>>();
    k_scatter<<<(T_TOK + 255) / 256, 256>>>();

    k_cvt_x<<<T_TOK * HDIM / 4 / 256, 256>>>(X);
    k_cvt_w13<<<NE * 1024 * 2048 / 256, 256>>>(W13);
    k_cvt_w2<<<NE * 2048 * 512 / 256, 256>>>(W2);

    k_gemm1<<<dim3(32, IDIM / 64, NE), 128, SMEM_BYTES>>>();
    k_gemm2<<<dim3(32, HDIM / 128, NE), 128, SMEM_BYTES>>>(out);
}